// round 10
// baseline (speedup 1.0000x reference)
#include <cuda_runtime.h>
#include <cuda_fp16.h>
#include <math.h>
#include <stdint.h>

#define B_SZ 2
#define T_SZ 2048
#define C_SZ 1024
#define NH   16
#define HD   64
#define M_SZ (B_SZ*T_SZ)   // 4096
#define LOG2E 1.44269504f

// Scratch (static device globals: allowed; runtime allocation is not)
__device__ __align__(256) __half   g_xh[M_SZ*C_SZ];           // x as fp16 [m][k]
__device__ __align__(256) uint32_t g_wt[4*C_SZ*(C_SZ/2)];     // W^T fp16 [w][n][k2] words
__device__ __align__(256) __half   g_qh[B_SZ*NH*T_SZ*HD];     // [bh][t][d]
__device__ __align__(256) uint32_t g_kw[B_SZ*NH*(HD/2)*T_SZ]; // [bh][d2][t] half2(d,d+1)
__device__ __align__(256) __half   g_vh[B_SZ*NH*T_SZ*HD];     // [bh][t][d]
__device__ __align__(256) __half   g_yh[M_SZ*C_SZ];           // attention out fp16 [m][c]

// ---------------------------------------------------------------------------
// helpers
// ---------------------------------------------------------------------------
__device__ __forceinline__ uint32_t pk(float lo, float hi){
    uint32_t r; asm("cvt.rn.f16x2.f32 %0, %1, %2;" : "=r"(r) : "f"(hi), "f"(lo));
    return r;
}
__device__ __forceinline__ uint32_t prmt(uint32_t a, uint32_t b, uint32_t sel){
    uint32_t r; asm("prmt.b32 %0, %1, %2, %3;" : "=r"(r) : "r"(a), "r"(b), "r"(sel));
    return r;
}
__device__ __forceinline__ uint32_t smem_u32(const void* p){
    uint32_t a;
    asm("{ .reg .u64 t; cvta.to.shared.u64 t, %1; cvt.u32.u64 %0, t; }"
        : "=r"(a) : "l"(p));
    return a;
}

// m16n8k16 fp16 mma, fp32 accumulate, D += A*B (C aliased to D)
__device__ __forceinline__ void mma16(float* d, const uint32_t* a, const uint32_t* b){
    asm volatile("mma.sync.aligned.m16n8k16.row.col.f32.f16.f16.f32 "
        "{%0,%1,%2,%3}, {%4,%5,%6,%7}, {%8,%9}, {%0,%1,%2,%3};"
        : "+f"(d[0]), "+f"(d[1]), "+f"(d[2]), "+f"(d[3])
        : "r"(a[0]), "r"(a[1]), "r"(a[2]), "r"(a[3]), "r"(b[0]), "r"(b[1]));
}

__device__ __forceinline__ void ldsm4(uint32_t* r, uint32_t saddr){
    asm volatile("ldmatrix.sync.aligned.m8n8.x4.shared.b16 {%0,%1,%2,%3}, [%4];"
        : "=r"(r[0]), "=r"(r[1]), "=r"(r[2]), "=r"(r[3]) : "r"(saddr));
}

// ---------------------------------------------------------------------------
// prep kernels: x -> fp16 [m][k]; W[k][n] fp32 -> W^T [n][k] fp16 words
// ---------------------------------------------------------------------------
__global__ void prep_x(const float* __restrict__ x, uint32_t* __restrict__ xh){
    const int i = blockIdx.x * blockDim.x + threadIdx.x;
    #pragma unroll
    for (int p = 0; p < 4; p++){
        float2 v = ((const float2*)x)[i + p*524288];
        xh[i + p*524288] = pk(v.x, v.y);
    }
}

__global__ void prep_w(const float* __restrict__ Wq, const float* __restrict__ Wk,
                       const float* __restrict__ Wv, const float* __restrict__ Wo,
                       uint32_t* __restrict__ Wt){
    __shared__ float s[64][65];
    const int wsel = blockIdx.z;
    const float* W = (wsel==0)?Wq:(wsel==1)?Wk:(wsel==2)?Wv:Wo;
    const int k0 = blockIdx.y*64, n0 = blockIdx.x*64;
    const int tid = threadIdx.x;
    #pragma unroll
    for (int p = 0; p < 16; p++){
        const int lin = tid + p*256, kk = lin >> 6, nn = lin & 63;
        s[kk][nn] = W[(size_t)(k0+kk)*C_SZ + n0 + nn];
    }
    __syncthreads();
    uint32_t* out = Wt + (size_t)wsel * C_SZ * (C_SZ/2);
    #pragma unroll
    for (int p = 0; p < 8; p++){
        const int lin = tid + p*256, nn = lin >> 5, k2 = lin & 31;
        out[(size_t)(n0+nn)*(C_SZ/2) + (k0 >> 1) + k2] = pk(s[2*k2][nn], s[2*k2+1][nn]);
    }
}

// ---------------------------------------------------------------------------
// fp16 ldmatrix GEMM: 128x128 tile, KC=64, 8 warps (4m x 2n), warp 32x64.
// Double-buffered dynamic smem (compile-time ping-pong), 1 barrier/K-step.
// Swizzle<3,3,3>: 16B chunk c -> c ^ (row&7). MODE 0 = QKV, MODE 1 = O-proj.
// ---------------------------------------------------------------------------
#define MODE_PLAIN   0
#define MODE_HEADS   1
#define MODE_HEADS_T 2
#define KC 64
#define GTILE 16384                 // 128 rows x 128 B
#define GDYN  (4*GTILE)             // A0 A1 B0 B1

template<int MODE>
__global__ __launch_bounds__(256, 2)
void lm_gemm(const __half* __restrict__ Aall, const uint32_t* __restrict__ Wt,
             const float* __restrict__ b0, const float* __restrict__ b1,
             const float* __restrict__ b2,
             void* __restrict__ o0, void* __restrict__ o1, void* __restrict__ o2)
{
    extern __shared__ char dsm[];
    uint4* Abuf[2] = { (uint4*)dsm,             (uint4*)(dsm + GTILE) };
    uint4* Bbuf[2] = { (uint4*)(dsm + 2*GTILE), (uint4*)(dsm + 3*GTILE) };
    const uint32_t sm0 = smem_u32(dsm);

    const int tid  = threadIdx.x;
    const int warp = tid >> 5, lane = tid & 31;
    const int gid  = lane >> 2, tig = lane & 3;
    const int warpM = (warp & 3) * 32, warpN = (warp >> 2) * 64;

    int which, bn, bm; const float* bias; void* outv;
    if (MODE == 0){
        which = blockIdx.x >> 3;
        bn = (blockIdx.x & 7) * 128;
        bm = blockIdx.y * 128;
        bias = (which==0)?b0:(which==1)?b1:b2;
        outv = (which==0)?o0:(which==1)?o1:o2;
    } else {
        which = 3; bn = blockIdx.x * 128; bm = blockIdx.y * 128;
        bias = b0; outv = o0;
    }
    const int mode = (MODE == 1) ? MODE_PLAIN : ((which == 1) ? MODE_HEADS_T : MODE_HEADS);

    const int a_m  = lane & 15, a_kg = lane >> 4;
    const int b_n  = (lane & 7) + ((lane >> 4) << 3);
    const int b_kg = (lane >> 3) & 1;
    const int lrow = tid >> 3, lseg = tid & 7;

    const __half*   Ah = Aall + (size_t)bm * C_SZ;
    const uint32_t* Bw = Wt + ((size_t)which * C_SZ + bn) * (C_SZ/2);

    uint4 pa[4], pb[4];
    auto LDG = [&](int k0){
        #pragma unroll
        for (int p = 0; p < 4; p++){
            const int row = lrow + 32*p;
            pa[p] = *(const uint4*)(Ah + (size_t)row*C_SZ + k0 + lseg*8);
            pb[p] = *(const uint4*)(Bw + (size_t)row*(C_SZ/2) + (k0>>1) + lseg*4);
        }
    };
    auto STS = [&](int buf){
        #pragma unroll
        for (int p = 0; p < 4; p++){
            const int row = lrow + 32*p;
            const int sc  = lseg ^ (row & 7);
            Abuf[buf][row*8 + sc] = pa[p];
            Bbuf[buf][row*8 + sc] = pb[p];
        }
    };

    float acc[2][8][4];
    #pragma unroll
    for (int mt = 0; mt < 2; mt++)
        #pragma unroll
        for (int nt = 0; nt < 8; nt++)
            #pragma unroll
            for (int e = 0; e < 4; e++) acc[mt][nt][e] = 0.f;

    auto COMPUTE = [&](int buf){
        const uint32_t Au = sm0 + buf*GTILE;
        const uint32_t Bu = sm0 + 2*GTILE + buf*GTILE;
        #pragma unroll
        for (int kw = 0; kw < KC; kw += 16){
            const int cb = kw >> 3;
            uint32_t a[2][4];
            #pragma unroll
            for (int mt = 0; mt < 2; mt++){
                const int row = warpM + mt*16 + a_m;
                ldsm4(a[mt], Au + row*128 + (((cb + a_kg) ^ (row & 7)) << 4));
            }
            #pragma unroll
            for (int j = 0; j < 4; j++){
                uint32_t bf[4];
                const int row = warpN + j*16 + b_n;
                ldsm4(bf, Bu + row*128 + (((cb + b_kg) ^ (row & 7)) << 4));
                mma16(acc[0][2*j  ], a[0], bf);
                mma16(acc[0][2*j+1], a[0], bf + 2);
                mma16(acc[1][2*j  ], a[1], bf);
                mma16(acc[1][2*j+1], a[1], bf + 2);
            }
        }
    };

    LDG(0); STS(0); LDG(KC);
    __syncthreads();
    for (int i = 0; i < 16; i += 2){
        STS(1);                                // regs: tile i+1 -> buf1
        if (i + 2 < 16) LDG((i+2)*KC);
        COMPUTE(0);                            // tile i
        __syncthreads();
        if (i + 2 < 16) STS(0);                // regs: tile i+2 -> buf0
        if (i + 3 < 16) LDG((i+3)*KC);
        COMPUTE(1);                            // tile i+1
        __syncthreads();
    }

    #pragma unroll
    for (int mt = 0; mt < 2; mt++){
        #pragma unroll
        for (int nt = 0; nt < 8; nt++){
            const int r = bm + warpM + mt*16 + gid;
            const int c = bn + warpN + nt*8 + 2*tig;
            const float b0v = bias[c], b1v = bias[c+1];
            float2 v0 = make_float2(acc[mt][nt][0] + b0v, acc[mt][nt][1] + b1v);
            float2 v1 = make_float2(acc[mt][nt][2] + b0v, acc[mt][nt][3] + b1v);
            if (mode == MODE_PLAIN){
                float* out = (float*)outv;
                *(float2*)&out[(size_t)r * C_SZ + c]     = v0;
                *(float2*)&out[(size_t)(r+8) * C_SZ + c] = v1;
            } else {
                const int b = r >> 11, t = r & 2047;
                const int h = c >> 6,  d = c & 63;
                const int bh = b*NH + h;
                if (mode == MODE_HEADS){
                    __half* out = (__half*)outv;
                    *(uint32_t*)&out[((size_t)bh * T_SZ + t    ) * HD + d] = pk(v0.x, v0.y);
                    *(uint32_t*)&out[((size_t)bh * T_SZ + t + 8) * HD + d] = pk(v1.x, v1.y);
                } else {
                    uint32_t* out = (uint32_t*)outv;
                    const size_t base = ((size_t)bh * (HD/2) + (d >> 1)) * T_SZ + t;
                    out[base]     = pk(v0.x, v0.y);
                    out[base + 8] = pk(v1.x, v1.y);
                }
            }
        }
    }
}

// ---------------------------------------------------------------------------
// Flash attention, fp16 mma, BQ=64, BK=128 (per-tile fixed costs halved),
// exp2-domain softmax. 128 thr (4 warps), 16 q-rows/warp.
// ---------------------------------------------------------------------------
#define SQW 36    // Qs [64 q][32+4]
#define SKW 136   // Ks [32 d2][128+8]
#define SVW 72    // Vs [64 t2][64+8]
#define SPW 68    // Ps [64 q][64+4]
#define FLASH_SMEM ((64*SQW + 32*SKW + 64*SVW + 64*SPW) * 4)

__global__ __launch_bounds__(128, 3)
void flash_tc(const __half* __restrict__ Q, const uint32_t* __restrict__ Kw,
              const __half* __restrict__ V, uint32_t* __restrict__ Yw)
{
    extern __shared__ uint32_t smbuf[];
    uint32_t* Qs = smbuf;
    uint32_t* Ks = Qs + 64*SQW;
    uint32_t* Vs = Ks + 32*SKW;
    uint32_t* Ps = Vs + 64*SVW;

    const int tid  = threadIdx.x;
    const int warp = tid >> 5, lane = tid & 31;
    const int gid  = lane >> 2, tig = lane & 3;
    const int qt   = (int)gridDim.x - 1 - (int)blockIdx.x;   // heavy first
    const int h    = blockIdx.y, b = blockIdx.z;
    const int bh   = b * NH + h;
    const int q0   = qt * 64;
    const int wrow = warp * 16;
    const float slope2 = exp2f(-0.5f * (float)(h + 1)) * LOG2E;  // log2-domain
    const float scale2 = 0.125f * LOG2E;

    {   // Q tile: raw copy, 64 rows x 32 words
        const uint32_t* qb = (const uint32_t*)(Q + ((size_t)bh * T_SZ + q0) * HD);
        const int qr = tid >> 3, qc = (tid & 7) * 4;
        #pragma unroll
        for (int p = 0; p < 4; p++)
            *(uint4*)&Qs[(qr + 16*p)*SQW + qc] = *(const uint4*)&qb[(qr + 16*p)*32 + qc];
    }

    const uint32_t* kb_base = Kw + (size_t)bh * (HD/2) * T_SZ;   // [d2][t]
    const __half*   vb_base = V  + (size_t)bh * T_SZ * HD;       // [t][d]

    const int klr = tid >> 5, kls = tid & 31;     // K loader: 4 rows/pass x 8
    const int vt2b = tid >> 2, vseg = tid & 3;    // V loader

    float m0 = -1e30f, m1 = -1e30f, l0 = 0.f, l1 = 0.f;
    float acc[8][4] = {};

    const int nkt = qt/2 + 1;
    for (int kt = 0; kt < nkt; kt++){
        const int k0 = kt * 128;
        __syncthreads();   // previous tile's matmuls done with Ks/Vs
        {   // K tile: raw word copy, 32 rows(d2) x 128 words(keys)
            #pragma unroll
            for (int p = 0; p < 8; p++){
                const int row = klr + 4*p;
                *(uint4*)&Ks[row*SKW + kls*4] =
                    *(const uint4*)&kb_base[(size_t)row * T_SZ + k0 + kls*4];
            }
            // V tile: merge adjacent-t rows into half2 pairs via PRMT, 64 t2-rows
            #pragma unroll
            for (int p = 0; p < 2; p++){
                const int t2 = vt2b + 32*p;
                const __half* v0p = vb_base + (size_t)(k0 + 2*t2) * HD + vseg*16;
                uint4 e0 = *(const uint4*)(v0p);
                uint4 e1 = *(const uint4*)(v0p + 8);
                uint4 o0 = *(const uint4*)(v0p + HD);
                uint4 o1 = *(const uint4*)(v0p + HD + 8);
                uint32_t* vd = &Vs[t2*SVW + vseg*16];
                *(uint4*)(vd   ) = make_uint4(prmt(e0.x,o0.x,0x5410), prmt(e0.x,o0.x,0x7632),
                                              prmt(e0.y,o0.y,0x5410), prmt(e0.y,o0.y,0x7632));
                *(uint4*)(vd+ 4) = make_uint4(prmt(e0.z,o0.z,0x5410), prmt(e0.z,o0.z,0x7632),
                                              prmt(e0.w,o0.w,0x5410), prmt(e0.w,o0.w,0x7632));
                *(uint4*)(vd+ 8) = make_uint4(prmt(e1.x,o1.x,0x5410), prmt(e1.x,o1.x,0x7632),
                                              prmt(e1.y,o1.y,0x5410), prmt(e1.y,o1.y,0x7632));
                *(uint4*)(vd+12) = make_uint4(prmt(e1.z,o1.z,0x5410), prmt(e1.z,o1.z,0x7632),
                                              prmt(e1.w,o1.w,0x5410), prmt(e1.w,o1.w,0x7632));
            }
        }
        __syncthreads();   // publish K/V (and Qs on iter 0)

        // S = Q K^T : 16 q-rows x 128 keys (4 k16 chunks x 16 n8 tiles)
        float s[16][4];
        #pragma unroll
        for (int nt = 0; nt < 16; nt++)
            #pragma unroll
            for (int e = 0; e < 4; e++) s[nt][e] = 0.f;
        #pragma unroll
        for (int ch = 0; ch < 4; ch++){
            const int kw = ch * 8;
            uint32_t af[4];
            af[0] = Qs[(wrow+gid  )*SQW + kw + tig];
            af[1] = Qs[(wrow+gid+8)*SQW + kw + tig];
            af[2] = Qs[(wrow+gid  )*SQW + kw + tig + 4];
            af[3] = Qs[(wrow+gid+8)*SQW + kw + tig + 4];
            #pragma unroll
            for (int nt = 0; nt < 16; nt++){
                uint32_t bf[2] = { Ks[(kw+tig)*SKW + nt*8 + gid],
                                   Ks[(kw+tig+4)*SKW + nt*8 + gid] };
                mma16(s[nt], af, bf);
            }
        }

        // log2-domain: score2 = s*scale2 + slope2*(ki-qi); online softmax
        const bool diag = (k0 + 127 > q0);
        const int qi0 = q0 + wrow + gid, qi1 = qi0 + 8;
        float mx0 = -1e30f, mx1 = -1e30f;
        #pragma unroll
        for (int nt = 0; nt < 16; nt++){
            #pragma unroll
            for (int e = 0; e < 2; e++){
                const int ki = k0 + nt*8 + 2*tig + e;
                float sv0 = fmaf(s[nt][e],   scale2, slope2 * (float)(ki - qi0));
                float sv1 = fmaf(s[nt][2+e], scale2, slope2 * (float)(ki - qi1));
                if (diag && ki > qi0) sv0 = -1e30f;
                if (diag && ki > qi1) sv1 = -1e30f;
                s[nt][e] = sv0; s[nt][2+e] = sv1;
                mx0 = fmaxf(mx0, sv0); mx1 = fmaxf(mx1, sv1);
            }
        }
        mx0 = fmaxf(mx0, __shfl_xor_sync(0xffffffffu, mx0, 1));
        mx0 = fmaxf(mx0, __shfl_xor_sync(0xffffffffu, mx0, 2));
        mx1 = fmaxf(mx1, __shfl_xor_sync(0xffffffffu, mx1, 1));
        mx1 = fmaxf(mx1, __shfl_xor_sync(0xffffffffu, mx1, 2));
        const float mn0 = fmaxf(m0, mx0), mn1 = fmaxf(m1, mx1);
        const float corr0 = exp2f(m0 - mn0), corr1 = exp2f(m1 - mn1);
        m0 = mn0; m1 = mn1;

        float ps0 = 0.f, ps1 = 0.f;
        #pragma unroll
        for (int nt = 0; nt < 16; nt++){
            const float p00 = exp2f(s[nt][0] - mn0), p01 = exp2f(s[nt][1] - mn0);
            const float p10 = exp2f(s[nt][2] - mn1), p11 = exp2f(s[nt][3] - mn1);
            ps0 += p00 + p01; ps1 += p10 + p11;
            Ps[(wrow+gid  )*SPW + nt*4 + tig] = pk(p00, p01);
            Ps[(wrow+gid+8)*SPW + nt*4 + tig] = pk(p10, p11);
        }
        ps0 += __shfl_xor_sync(0xffffffffu, ps0, 1);
        ps0 += __shfl_xor_sync(0xffffffffu, ps0, 2);
        ps1 += __shfl_xor_sync(0xffffffffu, ps1, 1);
        ps1 += __shfl_xor_sync(0xffffffffu, ps1, 2);
        l0 = l0 * corr0 + ps0;
        l1 = l1 * corr1 + ps1;
        #pragma unroll
        for (int nt = 0; nt < 8; nt++){
            acc[nt][0] *= corr0; acc[nt][1] *= corr0;
            acc[nt][2] *= corr1; acc[nt][3] *= corr1;
        }
        __syncwarp();   // Ps rows are warp-private

        // acc += P @ V (8 k16 chunks over 128 keys x 8 n8 tiles of d)
        #pragma unroll
        for (int ch = 0; ch < 8; ch++){
            const int kw = ch * 8;
            uint32_t af[4];
            af[0] = Ps[(wrow+gid  )*SPW + kw + tig];
            af[1] = Ps[(wrow+gid+8)*SPW + kw + tig];
            af[2] = Ps[(wrow+gid  )*SPW + kw + tig + 4];
            af[3] = Ps[(wrow+gid+8)*SPW + kw + tig + 4];
            #pragma unroll
            for (int nt = 0; nt < 8; nt++){
                uint32_t bf[2] = { Vs[(kw+tig)*SVW + nt*8 + gid],
                                   Vs[(kw+tig+4)*SVW + nt*8 + gid] };
                mma16(acc[nt], af, bf);
            }
        }
        __syncwarp();
    }

    const float i0 = 1.f / l0, i1 = 1.f / l1;
    const size_t mrow = (size_t)(b*T_SZ) + q0 + wrow;
    #pragma unroll
    for (int nt = 0; nt < 8; nt++){
        const int c = nt*8 + 2*tig;
        const int wc = (h*HD + c) >> 1;
        Yw[(mrow + gid    )*(C_SZ/2) + wc] = pk(acc[nt][0]*i0, acc[nt][1]*i0);
        Yw[(mrow + gid + 8)*(C_SZ/2) + wc] = pk(acc[nt][2]*i1, acc[nt][3]*i1);
    }
}

extern "C" void kernel_launch(void* const* d_in, const int* in_sizes, int n_in,
                              void* d_out, int out_size)
{
    const float* x  = (const float*)d_in[0];
    const float* Wq = (const float*)d_in[1];
    const float* bq = (const float*)d_in[2];
    const float* Wk = (const float*)d_in[3];
    const float* bk = (const float*)d_in[4];
    const float* Wv = (const float*)d_in[5];
    const float* bv = (const float*)d_in[6];
    const float* Wo = (const float*)d_in[7];
    const float* bo = (const float*)d_in[8];
    float* out = (float*)d_out;

    __half *xhp, *qp, *vp, *yhp; uint32_t *wtp, *ktp;
    cudaGetSymbolAddress((void**)&xhp, g_xh);
    cudaGetSymbolAddress((void**)&wtp, g_wt);
    cudaGetSymbolAddress((void**)&qp,  g_qh);
    cudaGetSymbolAddress((void**)&ktp, g_kw);
    cudaGetSymbolAddress((void**)&vp,  g_vh);
    cudaGetSymbolAddress((void**)&yhp, g_yh);

    cudaFuncSetAttribute(lm_gemm<0>, cudaFuncAttributeMaxDynamicSharedMemorySize, GDYN);
    cudaFuncSetAttribute(lm_gemm<1>, cudaFuncAttributeMaxDynamicSharedMemorySize, GDYN);
    cudaFuncSetAttribute(flash_tc, cudaFuncAttributeMaxDynamicSharedMemorySize, FLASH_SMEM);

    prep_x<<<2048, 256>>>(x, (uint32_t*)xhp);
    prep_w<<<dim3(16, 16, 4), 256>>>(Wq, Wk, Wv, Wo, wtp);

    lm_gemm<0><<<dim3(24, 32), 256, GDYN>>>(xhp, wtp, bq, bk, bv,
                                            (void*)qp, (void*)ktp, (void*)vp);

    flash_tc<<<dim3(T_SZ/64, NH, B_SZ), 128, FLASH_SMEM>>>(qp, ktp, vp, (uint32_t*)yhp);

    lm_gemm<1><<<dim3(8, 32), 256, GDYN>>>(yhp, wtp, bo, nullptr, nullptr,
                                           (void*)out, nullptr, nullptr);
}

// round 11
// speedup vs baseline: 1.0319x; 1.0319x over previous
#include <cuda_runtime.h>
#include <cuda_fp16.h>
#include <math.h>
#include <stdint.h>

#define B_SZ 2
#define T_SZ 2048
#define C_SZ 1024
#define NH   16
#define HD   64
#define M_SZ (B_SZ*T_SZ)   // 4096
#define LOG2E 1.44269504f

// Scratch (static device globals: allowed; runtime allocation is not)
__device__ __align__(256) __half   g_xh[M_SZ*C_SZ];           // x as fp16 [m][k]
__device__ __align__(256) uint32_t g_wt[4*C_SZ*(C_SZ/2)];     // W^T fp16 [w][n][k2] words
__device__ __align__(256) __half   g_qh[B_SZ*NH*T_SZ*HD];     // [bh][t][d]
__device__ __align__(256) uint32_t g_kw[B_SZ*NH*(HD/2)*T_SZ]; // [bh][d2][t] half2(d,d+1)
__device__ __align__(256) __half   g_vh[B_SZ*NH*T_SZ*HD];     // [bh][t][d]
__device__ __align__(256) __half   g_yh[M_SZ*C_SZ];           // attention out fp16 [m][c]

// ---------------------------------------------------------------------------
// helpers
// ---------------------------------------------------------------------------
__device__ __forceinline__ uint32_t pk(float lo, float hi){
    uint32_t r; asm("cvt.rn.f16x2.f32 %0, %1, %2;" : "=r"(r) : "f"(hi), "f"(lo));
    return r;
}
__device__ __forceinline__ uint32_t prmt(uint32_t a, uint32_t b, uint32_t sel){
    uint32_t r; asm("prmt.b32 %0, %1, %2, %3;" : "=r"(r) : "r"(a), "r"(b), "r"(sel));
    return r;
}
__device__ __forceinline__ uint32_t smem_u32(const void* p){
    uint32_t a;
    asm("{ .reg .u64 t; cvta.to.shared.u64 t, %1; cvt.u32.u64 %0, t; }"
        : "=r"(a) : "l"(p));
    return a;
}

// m16n8k16 fp16 mma, fp32 accumulate, D += A*B (C aliased to D)
__device__ __forceinline__ void mma16(float* d, const uint32_t* a, const uint32_t* b){
    asm volatile("mma.sync.aligned.m16n8k16.row.col.f32.f16.f16.f32 "
        "{%0,%1,%2,%3}, {%4,%5,%6,%7}, {%8,%9}, {%0,%1,%2,%3};"
        : "+f"(d[0]), "+f"(d[1]), "+f"(d[2]), "+f"(d[3])
        : "r"(a[0]), "r"(a[1]), "r"(a[2]), "r"(a[3]), "r"(b[0]), "r"(b[1]));
}

__device__ __forceinline__ void ldsm4(uint32_t* r, uint32_t saddr){
    asm volatile("ldmatrix.sync.aligned.m8n8.x4.shared.b16 {%0,%1,%2,%3}, [%4];"
        : "=r"(r[0]), "=r"(r[1]), "=r"(r[2]), "=r"(r[3]) : "r"(saddr));
}

// ---------------------------------------------------------------------------
// prep kernels: x -> fp16 [m][k]; W[k][n] fp32 -> W^T [n][k] fp16 words
// ---------------------------------------------------------------------------
__global__ void prep_x(const float* __restrict__ x, uint32_t* __restrict__ xh){
    const int i = blockIdx.x * blockDim.x + threadIdx.x;
    #pragma unroll
    for (int p = 0; p < 4; p++){
        float2 v = ((const float2*)x)[i + p*524288];
        xh[i + p*524288] = pk(v.x, v.y);
    }
}

__global__ void prep_w(const float* __restrict__ Wq, const float* __restrict__ Wk,
                       const float* __restrict__ Wv, const float* __restrict__ Wo,
                       uint32_t* __restrict__ Wt){
    __shared__ float s[64][65];
    const int wsel = blockIdx.z;
    const float* W = (wsel==0)?Wq:(wsel==1)?Wk:(wsel==2)?Wv:Wo;
    const int k0 = blockIdx.y*64, n0 = blockIdx.x*64;
    const int tid = threadIdx.x;
    #pragma unroll
    for (int p = 0; p < 16; p++){
        const int lin = tid + p*256, kk = lin >> 6, nn = lin & 63;
        s[kk][nn] = W[(size_t)(k0+kk)*C_SZ + n0 + nn];
    }
    __syncthreads();
    uint32_t* out = Wt + (size_t)wsel * C_SZ * (C_SZ/2);
    #pragma unroll
    for (int p = 0; p < 8; p++){
        const int lin = tid + p*256, nn = lin >> 5, k2 = lin & 31;
        out[(size_t)(n0+nn)*(C_SZ/2) + (k0 >> 1) + k2] = pk(s[2*k2][nn], s[2*k2+1][nn]);
    }
}

// ---------------------------------------------------------------------------
// fp16 ldmatrix GEMM: 128x128 tile, KC=64, 8 warps (4m x 2n), warp 32x64.
// Double-buffered dynamic smem (compile-time ping-pong), 1 barrier/K-step.
// Swizzle<3,3,3>: 16B chunk c -> c ^ (row&7). MODE 0 = QKV, MODE 1 = O-proj.
// ---------------------------------------------------------------------------
#define MODE_PLAIN   0
#define MODE_HEADS   1
#define MODE_HEADS_T 2
#define KC 64
#define GTILE 16384                 // 128 rows x 128 B
#define GDYN  (4*GTILE)             // A0 A1 B0 B1

template<int MODE>
__global__ __launch_bounds__(256, 2)
void lm_gemm(const __half* __restrict__ Aall, const uint32_t* __restrict__ Wt,
             const float* __restrict__ b0, const float* __restrict__ b1,
             const float* __restrict__ b2,
             void* __restrict__ o0, void* __restrict__ o1, void* __restrict__ o2)
{
    extern __shared__ char dsm[];
    uint4* Abuf[2] = { (uint4*)dsm,             (uint4*)(dsm + GTILE) };
    uint4* Bbuf[2] = { (uint4*)(dsm + 2*GTILE), (uint4*)(dsm + 3*GTILE) };
    const uint32_t sm0 = smem_u32(dsm);

    const int tid  = threadIdx.x;
    const int warp = tid >> 5, lane = tid & 31;
    const int gid  = lane >> 2, tig = lane & 3;
    const int warpM = (warp & 3) * 32, warpN = (warp >> 2) * 64;

    int which, bn, bm; const float* bias; void* outv;
    if (MODE == 0){
        which = blockIdx.x >> 3;
        bn = (blockIdx.x & 7) * 128;
        bm = blockIdx.y * 128;
        bias = (which==0)?b0:(which==1)?b1:b2;
        outv = (which==0)?o0:(which==1)?o1:o2;
    } else {
        which = 3; bn = blockIdx.x * 128; bm = blockIdx.y * 128;
        bias = b0; outv = o0;
    }
    const int mode = (MODE == 1) ? MODE_PLAIN : ((which == 1) ? MODE_HEADS_T : MODE_HEADS);

    const int a_m  = lane & 15, a_kg = lane >> 4;
    const int b_n  = (lane & 7) + ((lane >> 4) << 3);
    const int b_kg = (lane >> 3) & 1;
    const int lrow = tid >> 3, lseg = tid & 7;

    const __half*   Ah = Aall + (size_t)bm * C_SZ;
    const uint32_t* Bw = Wt + ((size_t)which * C_SZ + bn) * (C_SZ/2);

    uint4 pa[4], pb[4];
    auto LDG = [&](int k0){
        #pragma unroll
        for (int p = 0; p < 4; p++){
            const int row = lrow + 32*p;
            pa[p] = *(const uint4*)(Ah + (size_t)row*C_SZ + k0 + lseg*8);
            pb[p] = *(const uint4*)(Bw + (size_t)row*(C_SZ/2) + (k0>>1) + lseg*4);
        }
    };
    auto STS = [&](int buf){
        #pragma unroll
        for (int p = 0; p < 4; p++){
            const int row = lrow + 32*p;
            const int sc  = lseg ^ (row & 7);
            Abuf[buf][row*8 + sc] = pa[p];
            Bbuf[buf][row*8 + sc] = pb[p];
        }
    };

    float acc[2][8][4];
    #pragma unroll
    for (int mt = 0; mt < 2; mt++)
        #pragma unroll
        for (int nt = 0; nt < 8; nt++)
            #pragma unroll
            for (int e = 0; e < 4; e++) acc[mt][nt][e] = 0.f;

    auto COMPUTE = [&](int buf){
        const uint32_t Au = sm0 + buf*GTILE;
        const uint32_t Bu = sm0 + 2*GTILE + buf*GTILE;
        #pragma unroll
        for (int kw = 0; kw < KC; kw += 16){
            const int cb = kw >> 3;
            uint32_t a[2][4];
            #pragma unroll
            for (int mt = 0; mt < 2; mt++){
                const int row = warpM + mt*16 + a_m;
                ldsm4(a[mt], Au + row*128 + (((cb + a_kg) ^ (row & 7)) << 4));
            }
            #pragma unroll
            for (int j = 0; j < 4; j++){
                uint32_t bf[4];
                const int row = warpN + j*16 + b_n;
                ldsm4(bf, Bu + row*128 + (((cb + b_kg) ^ (row & 7)) << 4));
                mma16(acc[0][2*j  ], a[0], bf);
                mma16(acc[0][2*j+1], a[0], bf + 2);
                mma16(acc[1][2*j  ], a[1], bf);
                mma16(acc[1][2*j+1], a[1], bf + 2);
            }
        }
    };

    LDG(0); STS(0); LDG(KC);
    __syncthreads();
    for (int i = 0; i < 16; i += 2){
        STS(1);                                // regs: tile i+1 -> buf1
        if (i + 2 < 16) LDG((i+2)*KC);
        COMPUTE(0);                            // tile i
        __syncthreads();
        if (i + 2 < 16) STS(0);                // regs: tile i+2 -> buf0
        if (i + 3 < 16) LDG((i+3)*KC);
        COMPUTE(1);                            // tile i+1
        __syncthreads();
    }

    #pragma unroll
    for (int mt = 0; mt < 2; mt++){
        #pragma unroll
        for (int nt = 0; nt < 8; nt++){
            const int r = bm + warpM + mt*16 + gid;
            const int c = bn + warpN + nt*8 + 2*tig;
            const float b0v = bias[c], b1v = bias[c+1];
            float2 v0 = make_float2(acc[mt][nt][0] + b0v, acc[mt][nt][1] + b1v);
            float2 v1 = make_float2(acc[mt][nt][2] + b0v, acc[mt][nt][3] + b1v);
            if (mode == MODE_PLAIN){
                float* out = (float*)outv;
                *(float2*)&out[(size_t)r * C_SZ + c]     = v0;
                *(float2*)&out[(size_t)(r+8) * C_SZ + c] = v1;
            } else {
                const int b = r >> 11, t = r & 2047;
                const int h = c >> 6,  d = c & 63;
                const int bh = b*NH + h;
                if (mode == MODE_HEADS){
                    __half* out = (__half*)outv;
                    *(uint32_t*)&out[((size_t)bh * T_SZ + t    ) * HD + d] = pk(v0.x, v0.y);
                    *(uint32_t*)&out[((size_t)bh * T_SZ + t + 8) * HD + d] = pk(v1.x, v1.y);
                } else {
                    uint32_t* out = (uint32_t*)outv;
                    const size_t base = ((size_t)bh * (HD/2) + (d >> 1)) * T_SZ + t;
                    out[base]     = pk(v0.x, v0.y);
                    out[base + 8] = pk(v1.x, v1.y);
                }
            }
        }
    }
}

// ---------------------------------------------------------------------------
// Flash attention, fp16 mma, BQ=64, BK=64, P kept in REGISTERS (FA-2 style):
// the S-mma C-fragment layout equals the P@V A-fragment layout, so P never
// touches smem (no Ps tile, no syncwarp). exp2-domain softmax.
// ---------------------------------------------------------------------------
#define SQW 36    // Qs [64 q][32+4]
#define SKW 72    // Ks [32 d2][64+8], Vs [32 t2][64+8]
#define FLASH_SMEM ((64*SQW + 32*SKW + 32*SKW) * 4)

__global__ __launch_bounds__(128, 4)
void flash_tc(const __half* __restrict__ Q, const uint32_t* __restrict__ Kw,
              const __half* __restrict__ V, uint32_t* __restrict__ Yw)
{
    extern __shared__ uint32_t smbuf[];
    uint32_t* Qs = smbuf;
    uint32_t* Ks = Qs + 64*SQW;
    uint32_t* Vs = Ks + 32*SKW;

    const int tid  = threadIdx.x;
    const int warp = tid >> 5, lane = tid & 31;
    const int gid  = lane >> 2, tig = lane & 3;
    const int qt   = (int)gridDim.x - 1 - (int)blockIdx.x;   // heavy first
    const int h    = blockIdx.y, b = blockIdx.z;
    const int bh   = b * NH + h;
    const int q0   = qt * 64;
    const int wrow = warp * 16;
    const float slope2 = exp2f(-0.5f * (float)(h + 1)) * LOG2E;
    const float scale2 = 0.125f * LOG2E;

    {   // Q tile: raw copy, 64 rows x 32 words
        const uint32_t* qb = (const uint32_t*)(Q + ((size_t)bh * T_SZ + q0) * HD);
        const int qr = tid >> 3, qc = (tid & 7) * 4;
        #pragma unroll
        for (int p = 0; p < 4; p++)
            *(uint4*)&Qs[(qr + 16*p)*SQW + qc] = *(const uint4*)&qb[(qr + 16*p)*32 + qc];
    }

    const uint32_t* kb_base = Kw + (size_t)bh * (HD/2) * T_SZ;   // [d2][t]
    const __half*   vb_base = V  + (size_t)bh * T_SZ * HD;       // [t][d]

    const int kr = tid >> 4, kc = (tid & 15) * 4;
    const int vt2 = tid >> 2, vseg = tid & 3;

    float m0 = -1e30f, m1 = -1e30f, l0 = 0.f, l1 = 0.f;
    float acc[8][4] = {};

    const int nkt = qt + 1;
    for (int kt = 0; kt < nkt; kt++){
        const int k0 = kt * 64;
        __syncthreads();   // previous tile's matmuls done with Ks/Vs
        {
            #pragma unroll
            for (int p = 0; p < 4; p++)
                *(uint4*)&Ks[(kr + 8*p)*SKW + kc] =
                    *(const uint4*)&kb_base[(size_t)(kr + 8*p) * T_SZ + k0 + kc];
            const __half* v0p = vb_base + (size_t)(k0 + 2*vt2) * HD + vseg*16;
            uint4 e0 = *(const uint4*)(v0p);
            uint4 e1 = *(const uint4*)(v0p + 8);
            uint4 o0 = *(const uint4*)(v0p + HD);
            uint4 o1 = *(const uint4*)(v0p + HD + 8);
            uint32_t* vd = &Vs[vt2*SKW + vseg*16];
            *(uint4*)(vd    ) = make_uint4(prmt(e0.x,o0.x,0x5410), prmt(e0.x,o0.x,0x7632),
                                           prmt(e0.y,o0.y,0x5410), prmt(e0.y,o0.y,0x7632));
            *(uint4*)(vd + 4) = make_uint4(prmt(e0.z,o0.z,0x5410), prmt(e0.z,o0.z,0x7632),
                                           prmt(e0.w,o0.w,0x5410), prmt(e0.w,o0.w,0x7632));
            *(uint4*)(vd + 8) = make_uint4(prmt(e1.x,o1.x,0x5410), prmt(e1.x,o1.x,0x7632),
                                           prmt(e1.y,o1.y,0x5410), prmt(e1.y,o1.y,0x7632));
            *(uint4*)(vd +12) = make_uint4(prmt(e1.z,o1.z,0x5410), prmt(e1.z,o1.z,0x7632),
                                           prmt(e1.w,o1.w,0x5410), prmt(e1.w,o1.w,0x7632));
        }
        __syncthreads();   // publish K/V (and Qs on iter 0)

        // S = Q K^T : warp computes its 16 rows x 64 keys (4 k16 chunks)
        float s[8][4] = {};
        #pragma unroll
        for (int ch = 0; ch < 4; ch++){
            const int kw = ch * 8;
            uint32_t af[4];
            af[0] = Qs[(wrow+gid  )*SQW + kw + tig];
            af[1] = Qs[(wrow+gid+8)*SQW + kw + tig];
            af[2] = Qs[(wrow+gid  )*SQW + kw + tig + 4];
            af[3] = Qs[(wrow+gid+8)*SQW + kw + tig + 4];
            #pragma unroll
            for (int nt = 0; nt < 8; nt++){
                uint32_t bf[2] = { Ks[(kw+tig)*SKW + nt*8 + gid],
                                   Ks[(kw+tig+4)*SKW + nt*8 + gid] };
                mma16(s[nt], af, bf);
            }
        }

        // log2-domain ALiBi + causal + online softmax (all in fragments)
        const bool diag = (kt == nkt - 1);
        const int qi0 = q0 + wrow + gid, qi1 = qi0 + 8;
        float mx0 = -1e30f, mx1 = -1e30f;
        #pragma unroll
        for (int nt = 0; nt < 8; nt++){
            #pragma unroll
            for (int e = 0; e < 2; e++){
                const int ki = k0 + nt*8 + 2*tig + e;
                float sv0 = fmaf(s[nt][e],   scale2, slope2 * (float)(ki - qi0));
                float sv1 = fmaf(s[nt][2+e], scale2, slope2 * (float)(ki - qi1));
                if (diag && ki > qi0) sv0 = -1e30f;
                if (diag && ki > qi1) sv1 = -1e30f;
                s[nt][e] = sv0; s[nt][2+e] = sv1;
                mx0 = fmaxf(mx0, sv0); mx1 = fmaxf(mx1, sv1);
            }
        }
        mx0 = fmaxf(mx0, __shfl_xor_sync(0xffffffffu, mx0, 1));
        mx0 = fmaxf(mx0, __shfl_xor_sync(0xffffffffu, mx0, 2));
        mx1 = fmaxf(mx1, __shfl_xor_sync(0xffffffffu, mx1, 1));
        mx1 = fmaxf(mx1, __shfl_xor_sync(0xffffffffu, mx1, 2));
        const float mn0 = fmaxf(m0, mx0), mn1 = fmaxf(m1, mx1);
        const float corr0 = exp2f(m0 - mn0), corr1 = exp2f(m1 - mn1);
        m0 = mn0; m1 = mn1;

        // exp + pack P directly into A-fragments (C-frag layout == A-frag layout)
        uint32_t pfr[4][4];
        float ps0 = 0.f, ps1 = 0.f;
        #pragma unroll
        for (int nt = 0; nt < 8; nt++){
            const float p00 = exp2f(s[nt][0] - mn0), p01 = exp2f(s[nt][1] - mn0);
            const float p10 = exp2f(s[nt][2] - mn1), p11 = exp2f(s[nt][3] - mn1);
            ps0 += p00 + p01; ps1 += p10 + p11;
            const int ch = nt >> 1, hi = nt & 1;   // keys nt*8.. -> chunk nt/2, half nt%2
            pfr[ch][2*hi    ] = pk(p00, p01);      // row gid,   k-halves (8hi+2tig)
            pfr[ch][2*hi + 1] = pk(p10, p11);      // row gid+8
        }
        ps0 += __shfl_xor_sync(0xffffffffu, ps0, 1);
        ps0 += __shfl_xor_sync(0xffffffffu, ps0, 2);
        ps1 += __shfl_xor_sync(0xffffffffu, ps1, 1);
        ps1 += __shfl_xor_sync(0xffffffffu, ps1, 2);
        l0 = l0 * corr0 + ps0;
        l1 = l1 * corr1 + ps1;
        #pragma unroll
        for (int nt = 0; nt < 8; nt++){
            acc[nt][0] *= corr0; acc[nt][1] *= corr0;
            acc[nt][2] *= corr1; acc[nt][3] *= corr1;
        }

        // acc += P @ V, P straight from registers (4 k16 chunks over 64 keys)
        #pragma unroll
        for (int ch = 0; ch < 4; ch++){
            const int kw = ch * 8;
            #pragma unroll
            for (int nt = 0; nt < 8; nt++){
                uint32_t bf[2] = { Vs[(kw+tig)*SKW + nt*8 + gid],
                                   Vs[(kw+tig+4)*SKW + nt*8 + gid] };
                mma16(acc[nt], pfr[ch], bf);
            }
        }
    }

    const float i0 = 1.f / l0, i1 = 1.f / l1;
    const size_t mrow = (size_t)(b*T_SZ) + q0 + wrow;
    #pragma unroll
    for (int nt = 0; nt < 8; nt++){
        const int c = nt*8 + 2*tig;
        const int wc = (h*HD + c) >> 1;
        Yw[(mrow + gid    )*(C_SZ/2) + wc] = pk(acc[nt][0]*i0, acc[nt][1]*i0);
        Yw[(mrow + gid + 8)*(C_SZ/2) + wc] = pk(acc[nt][2]*i1, acc[nt][3]*i1);
    }
}

extern "C" void kernel_launch(void* const* d_in, const int* in_sizes, int n_in,
                              void* d_out, int out_size)
{
    const float* x  = (const float*)d_in[0];
    const float* Wq = (const float*)d_in[1];
    const float* bq = (const float*)d_in[2];
    const float* Wk = (const float*)d_in[3];
    const float* bk = (const float*)d_in[4];
    const float* Wv = (const float*)d_in[5];
    const float* bv = (const float*)d_in[6];
    const float* Wo = (const float*)d_in[7];
    const float* bo = (const float*)d_in[8];
    float* out = (float*)d_out;

    __half *xhp, *qp, *vp, *yhp; uint32_t *wtp, *ktp;
    cudaGetSymbolAddress((void**)&xhp, g_xh);
    cudaGetSymbolAddress((void**)&wtp, g_wt);
    cudaGetSymbolAddress((void**)&qp,  g_qh);
    cudaGetSymbolAddress((void**)&ktp, g_kw);
    cudaGetSymbolAddress((void**)&vp,  g_vh);
    cudaGetSymbolAddress((void**)&yhp, g_yh);

    cudaFuncSetAttribute(lm_gemm<0>, cudaFuncAttributeMaxDynamicSharedMemorySize, GDYN);
    cudaFuncSetAttribute(lm_gemm<1>, cudaFuncAttributeMaxDynamicSharedMemorySize, GDYN);
    cudaFuncSetAttribute(flash_tc, cudaFuncAttributeMaxDynamicSharedMemorySize, FLASH_SMEM);

    prep_x<<<2048, 256>>>(x, (uint32_t*)xhp);
    prep_w<<<dim3(16, 16, 4), 256>>>(Wq, Wk, Wv, Wo, wtp);

    lm_gemm<0><<<dim3(24, 32), 256, GDYN>>>(xhp, wtp, bq, bk, bv,
                                            (void*)qp, (void*)ktp, (void*)vp);

    flash_tc<<<dim3(T_SZ/64, NH, B_SZ), 128, FLASH_SMEM>>>(qp, ktp, vp, (uint32_t*)yhp);

    lm_gemm<1><<<dim3(8, 32), 256, GDYN>>>(yhp, wtp, bo, nullptr, nullptr,
                                           (void*)out, nullptr, nullptr);
}

// round 12
// speedup vs baseline: 1.0938x; 1.0601x over previous
#include <cuda_runtime.h>
#include <cuda_fp16.h>
#include <math.h>
#include <stdint.h>

#define B_SZ 2
#define T_SZ 2048
#define C_SZ 1024
#define NH   16
#define HD   64
#define M_SZ (B_SZ*T_SZ)   // 4096
#define LOG2E 1.44269504f

// Scratch (static device globals: allowed; runtime allocation is not)
__device__ __align__(256) __half   g_xh[M_SZ*C_SZ];           // x as fp16 [m][k]
__device__ __align__(256) uint32_t g_wt[4*C_SZ*(C_SZ/2)];     // W^T fp16 [w][n][k2] words
__device__ __align__(256) __half   g_qh[B_SZ*NH*T_SZ*HD];     // [bh][t][d]
__device__ __align__(256) __half   g_kh[B_SZ*NH*T_SZ*HD];     // [bh][t][d]
__device__ __align__(256) __half   g_vh[B_SZ*NH*T_SZ*HD];     // [bh][t][d]
__device__ __align__(256) __half   g_yh[M_SZ*C_SZ];           // attention out fp16 [m][c]

// ---------------------------------------------------------------------------
// helpers
// ---------------------------------------------------------------------------
__device__ __forceinline__ uint32_t pk(float lo, float hi){
    uint32_t r; asm("cvt.rn.f16x2.f32 %0, %1, %2;" : "=r"(r) : "f"(hi), "f"(lo));
    return r;
}
__device__ __forceinline__ uint32_t smem_u32(const void* p){
    uint32_t a;
    asm("{ .reg .u64 t; cvta.to.shared.u64 t, %1; cvt.u32.u64 %0, t; }"
        : "=r"(a) : "l"(p));
    return a;
}

// m16n8k16 fp16 mma, fp32 accumulate, D += A*B (C aliased to D)
__device__ __forceinline__ void mma16(float* d, const uint32_t* a, const uint32_t* b){
    asm volatile("mma.sync.aligned.m16n8k16.row.col.f32.f16.f16.f32 "
        "{%0,%1,%2,%3}, {%4,%5,%6,%7}, {%8,%9}, {%0,%1,%2,%3};"
        : "+f"(d[0]), "+f"(d[1]), "+f"(d[2]), "+f"(d[3])
        : "r"(a[0]), "r"(a[1]), "r"(a[2]), "r"(a[3]), "r"(b[0]), "r"(b[1]));
}

__device__ __forceinline__ void ldsm4(uint32_t* r, uint32_t saddr){
    asm volatile("ldmatrix.sync.aligned.m8n8.x4.shared.b16 {%0,%1,%2,%3}, [%4];"
        : "=r"(r[0]), "=r"(r[1]), "=r"(r[2]), "=r"(r[3]) : "r"(saddr));
}
__device__ __forceinline__ void ldsm4t(uint32_t* r, uint32_t saddr){
    asm volatile("ldmatrix.sync.aligned.m8n8.x4.trans.shared.b16 {%0,%1,%2,%3}, [%4];"
        : "=r"(r[0]), "=r"(r[1]), "=r"(r[2]), "=r"(r[3]) : "r"(saddr));
}

// ---------------------------------------------------------------------------
// prep kernels: x -> fp16 [m][k]; W[k][n] fp32 -> W^T [n][k] fp16 words
// ---------------------------------------------------------------------------
__global__ void prep_x(const float* __restrict__ x, uint32_t* __restrict__ xh){
    const int i = blockIdx.x * blockDim.x + threadIdx.x;
    #pragma unroll
    for (int p = 0; p < 4; p++){
        float2 v = ((const float2*)x)[i + p*524288];
        xh[i + p*524288] = pk(v.x, v.y);
    }
}

__global__ void prep_w(const float* __restrict__ Wq, const float* __restrict__ Wk,
                       const float* __restrict__ Wv, const float* __restrict__ Wo,
                       uint32_t* __restrict__ Wt){
    __shared__ float s[64][65];
    const int wsel = blockIdx.z;
    const float* W = (wsel==0)?Wq:(wsel==1)?Wk:(wsel==2)?Wv:Wo;
    const int k0 = blockIdx.y*64, n0 = blockIdx.x*64;
    const int tid = threadIdx.x;
    #pragma unroll
    for (int p = 0; p < 16; p++){
        const int lin = tid + p*256, kk = lin >> 6, nn = lin & 63;
        s[kk][nn] = W[(size_t)(k0+kk)*C_SZ + n0 + nn];
    }
    __syncthreads();
    uint32_t* out = Wt + (size_t)wsel * C_SZ * (C_SZ/2);
    #pragma unroll
    for (int p = 0; p < 8; p++){
        const int lin = tid + p*256, nn = lin >> 5, k2 = lin & 31;
        out[(size_t)(n0+nn)*(C_SZ/2) + (k0 >> 1) + k2] = pk(s[2*k2][nn], s[2*k2+1][nn]);
    }
}

// ---------------------------------------------------------------------------
// fp16 ldmatrix GEMM: 128x128 tile, KC=64, 8 warps (4m x 2n), warp 32x64.
// Double-buffered dynamic smem (compile-time ping-pong), 1 barrier/K-step.
// Swizzle<3,3,3>: 16B chunk c -> c ^ (row&7). MODE 0 = QKV, MODE 1 = O-proj.
// ---------------------------------------------------------------------------
#define MODE_PLAIN   0
#define MODE_HEADS   1
#define KC 64
#define GTILE 16384                 // 128 rows x 128 B
#define GDYN  (4*GTILE)             // A0 A1 B0 B1

template<int MODE>
__global__ __launch_bounds__(256, 2)
void lm_gemm(const __half* __restrict__ Aall, const uint32_t* __restrict__ Wt,
             const float* __restrict__ b0, const float* __restrict__ b1,
             const float* __restrict__ b2,
             void* __restrict__ o0, void* __restrict__ o1, void* __restrict__ o2)
{
    extern __shared__ char dsm[];
    uint4* Abuf[2] = { (uint4*)dsm,             (uint4*)(dsm + GTILE) };
    uint4* Bbuf[2] = { (uint4*)(dsm + 2*GTILE), (uint4*)(dsm + 3*GTILE) };
    const uint32_t sm0 = smem_u32(dsm);

    const int tid  = threadIdx.x;
    const int warp = tid >> 5, lane = tid & 31;
    const int gid  = lane >> 2, tig = lane & 3;
    const int warpM = (warp & 3) * 32, warpN = (warp >> 2) * 64;

    int which, bn, bm; const float* bias; void* outv;
    if (MODE == 0){
        which = blockIdx.x >> 3;
        bn = (blockIdx.x & 7) * 128;
        bm = blockIdx.y * 128;
        bias = (which==0)?b0:(which==1)?b1:b2;
        outv = (which==0)?o0:(which==1)?o1:o2;
    } else {
        which = 3; bn = blockIdx.x * 128; bm = blockIdx.y * 128;
        bias = b0; outv = o0;
    }

    const int a_m  = lane & 15, a_kg = lane >> 4;
    const int b_n  = (lane & 7) + ((lane >> 4) << 3);
    const int b_kg = (lane >> 3) & 1;
    const int lrow = tid >> 3, lseg = tid & 7;

    const __half*   Ah = Aall + (size_t)bm * C_SZ;
    const uint32_t* Bw = Wt + ((size_t)which * C_SZ + bn) * (C_SZ/2);

    uint4 pa[4], pb[4];
    auto LDG = [&](int k0){
        #pragma unroll
        for (int p = 0; p < 4; p++){
            const int row = lrow + 32*p;
            pa[p] = *(const uint4*)(Ah + (size_t)row*C_SZ + k0 + lseg*8);
            pb[p] = *(const uint4*)(Bw + (size_t)row*(C_SZ/2) + (k0>>1) + lseg*4);
        }
    };
    auto STS = [&](int buf){
        #pragma unroll
        for (int p = 0; p < 4; p++){
            const int row = lrow + 32*p;
            const int sc  = lseg ^ (row & 7);
            Abuf[buf][row*8 + sc] = pa[p];
            Bbuf[buf][row*8 + sc] = pb[p];
        }
    };

    float acc[2][8][4];
    #pragma unroll
    for (int mt = 0; mt < 2; mt++)
        #pragma unroll
        for (int nt = 0; nt < 8; nt++)
            #pragma unroll
            for (int e = 0; e < 4; e++) acc[mt][nt][e] = 0.f;

    auto COMPUTE = [&](int buf){
        const uint32_t Au = sm0 + buf*GTILE;
        const uint32_t Bu = sm0 + 2*GTILE + buf*GTILE;
        #pragma unroll
        for (int kw = 0; kw < KC; kw += 16){
            const int cb = kw >> 3;
            uint32_t a[2][4];
            #pragma unroll
            for (int mt = 0; mt < 2; mt++){
                const int row = warpM + mt*16 + a_m;
                ldsm4(a[mt], Au + row*128 + (((cb + a_kg) ^ (row & 7)) << 4));
            }
            #pragma unroll
            for (int j = 0; j < 4; j++){
                uint32_t bf[4];
                const int row = warpN + j*16 + b_n;
                ldsm4(bf, Bu + row*128 + (((cb + b_kg) ^ (row & 7)) << 4));
                mma16(acc[0][2*j  ], a[0], bf);
                mma16(acc[0][2*j+1], a[0], bf + 2);
                mma16(acc[1][2*j  ], a[1], bf);
                mma16(acc[1][2*j+1], a[1], bf + 2);
            }
        }
    };

    LDG(0); STS(0); LDG(KC);
    __syncthreads();
    for (int i = 0; i < 16; i += 2){
        STS(1);
        if (i + 2 < 16) LDG((i+2)*KC);
        COMPUTE(0);
        __syncthreads();
        if (i + 2 < 16) STS(0);
        if (i + 3 < 16) LDG((i+3)*KC);
        COMPUTE(1);
        __syncthreads();
    }

    #pragma unroll
    for (int mt = 0; mt < 2; mt++){
        #pragma unroll
        for (int nt = 0; nt < 8; nt++){
            const int r = bm + warpM + mt*16 + gid;
            const int c = bn + warpN + nt*8 + 2*tig;
            const float b0v = bias[c], b1v = bias[c+1];
            float2 v0 = make_float2(acc[mt][nt][0] + b0v, acc[mt][nt][1] + b1v);
            float2 v1 = make_float2(acc[mt][nt][2] + b0v, acc[mt][nt][3] + b1v);
            if (MODE == 1){
                float* out = (float*)outv;
                *(float2*)&out[(size_t)r * C_SZ + c]     = v0;
                *(float2*)&out[(size_t)(r+8) * C_SZ + c] = v1;
            } else {
                const int b = r >> 11, t = r & 2047;
                const int h = c >> 6,  d = c & 63;
                const int bh = b*NH + h;
                __half* out = (__half*)outv;
                *(uint32_t*)&out[((size_t)bh * T_SZ + t    ) * HD + d] = pk(v0.x, v0.y);
                *(uint32_t*)&out[((size_t)bh * T_SZ + t + 8) * HD + d] = pk(v1.x, v1.y);
            }
        }
    }
}

// ---------------------------------------------------------------------------
// Flash attention, fp16 mma, BQ=64, BK=64, P in registers (FA-2 style),
// ALL fragment loads via ldmatrix: Q/K non-trans, V trans (V is [t][d] =
// [k][n] row-major for the P@V B-operand). Q/K/V smem tiles are identical
// raw swizzled copies (Swizzle<3,3,3>, 128B rows). exp2-domain softmax.
// ---------------------------------------------------------------------------
#define FTILE 8192   // 64 rows x 128 B
#define FLASH_SMEM (3*FTILE)

__global__ __launch_bounds__(128, 4)
void flash_tc(const __half* __restrict__ Q, const __half* __restrict__ K,
              const __half* __restrict__ V, uint32_t* __restrict__ Yw)
{
    extern __shared__ char fsm[];
    const uint32_t Qu = smem_u32(fsm);
    const uint32_t Ku = Qu + FTILE;
    const uint32_t Vu = Qu + 2*FTILE;
    uint4* Qs = (uint4*)fsm;
    uint4* Ks = (uint4*)(fsm + FTILE);
    uint4* Vs = (uint4*)(fsm + 2*FTILE);

    const int tid  = threadIdx.x;
    const int warp = tid >> 5, lane = tid & 31;
    const int gid  = lane >> 2, tig = lane & 3;
    const int qt   = (int)gridDim.x - 1 - (int)blockIdx.x;   // heavy first
    const int h    = blockIdx.y, b = blockIdx.z;
    const int bh   = b * NH + h;
    const int q0   = qt * 64;
    const int wrow = warp * 16;
    const float slope2 = exp2f(-0.5f * (float)(h + 1)) * LOG2E;
    const float scale2 = 0.125f * LOG2E;

    // ldmatrix lane-constant coords
    const int a_m  = lane & 15, a_kg = lane >> 4;           // A-frag (Q)
    const int b_n  = (lane & 7) + ((lane >> 4) << 3);       // B-frag non-trans (K)
    const int b_kg = (lane >> 3) & 1;
    const int vt_k = (lane & 7) + (((lane >> 3) & 1) << 3); // B-frag trans (V): k row
    const int vt_n = (lane >> 4);                           // n8-half within n16

    // loader coords: 64 rows x 8 chunks = 512 uint4, 128 thr -> 4 passes
    const int lrow = tid >> 3, lseg = tid & 7;

    const __half* qb = Q + ((size_t)bh * T_SZ + q0) * HD;
    const __half* kb = K + (size_t)bh * T_SZ * HD;
    const __half* vb = V + (size_t)bh * T_SZ * HD;

    {   // Q tile: raw swizzled copy
        #pragma unroll
        for (int p = 0; p < 4; p++){
            const int row = lrow + 16*p;
            Qs[row*8 + (lseg ^ (row & 7))] = *(const uint4*)(qb + (size_t)row*HD + lseg*8);
        }
    }

    float m0 = -1e30f, m1 = -1e30f, l0 = 0.f, l1 = 0.f;
    float acc[8][4] = {};

    const int nkt = qt + 1;
    for (int kt = 0; kt < nkt; kt++){
        const int k0 = kt * 64;
        __syncthreads();   // previous tile's matmuls done with Ks/Vs
        #pragma unroll
        for (int p = 0; p < 4; p++){
            const int row = lrow + 16*p;
            const int sc  = row*8 + (lseg ^ (row & 7));
            Ks[sc] = *(const uint4*)(kb + (size_t)(k0 + row)*HD + lseg*8);
            Vs[sc] = *(const uint4*)(vb + (size_t)(k0 + row)*HD + lseg*8);
        }
        __syncthreads();   // publish K/V (and Qs on iter 0)

        // S = Q K^T : warp's 16 q-rows x 64 keys (4 k16 chunks)
        float s[8][4] = {};
        #pragma unroll
        for (int ch = 0; ch < 4; ch++){
            const int cb = ch * 2;
            uint32_t af[4];
            {
                const int row = wrow + a_m;
                ldsm4(af, Qu + row*128 + (((cb + a_kg) ^ (row & 7)) << 4));
            }
            #pragma unroll
            for (int j = 0; j < 4; j++){
                uint32_t bf[4];
                const int row = j*16 + b_n;
                ldsm4(bf, Ku + row*128 + (((cb + b_kg) ^ (row & 7)) << 4));
                mma16(s[2*j  ], af, bf);
                mma16(s[2*j+1], af, bf + 2);
            }
        }

        // log2-domain ALiBi + causal + online softmax (all in fragments)
        const bool diag = (kt == nkt - 1);
        const int qi0 = q0 + wrow + gid, qi1 = qi0 + 8;
        float mx0 = -1e30f, mx1 = -1e30f;
        #pragma unroll
        for (int nt = 0; nt < 8; nt++){
            #pragma unroll
            for (int e = 0; e < 2; e++){
                const int ki = k0 + nt*8 + 2*tig + e;
                float sv0 = fmaf(s[nt][e],   scale2, slope2 * (float)(ki - qi0));
                float sv1 = fmaf(s[nt][2+e], scale2, slope2 * (float)(ki - qi1));
                if (diag && ki > qi0) sv0 = -1e30f;
                if (diag && ki > qi1) sv1 = -1e30f;
                s[nt][e] = sv0; s[nt][2+e] = sv1;
                mx0 = fmaxf(mx0, sv0); mx1 = fmaxf(mx1, sv1);
            }
        }
        mx0 = fmaxf(mx0, __shfl_xor_sync(0xffffffffu, mx0, 1));
        mx0 = fmaxf(mx0, __shfl_xor_sync(0xffffffffu, mx0, 2));
        mx1 = fmaxf(mx1, __shfl_xor_sync(0xffffffffu, mx1, 1));
        mx1 = fmaxf(mx1, __shfl_xor_sync(0xffffffffu, mx1, 2));
        const float mn0 = fmaxf(m0, mx0), mn1 = fmaxf(m1, mx1);
        const float corr0 = exp2f(m0 - mn0), corr1 = exp2f(m1 - mn1);
        m0 = mn0; m1 = mn1;

        // exp + pack P into A-fragments (C-frag layout == A-frag layout)
        uint32_t pfr[4][4];
        float ps0 = 0.f, ps1 = 0.f;
        #pragma unroll
        for (int nt = 0; nt < 8; nt++){
            const float p00 = exp2f(s[nt][0] - mn0), p01 = exp2f(s[nt][1] - mn0);
            const float p10 = exp2f(s[nt][2] - mn1), p11 = exp2f(s[nt][3] - mn1);
            ps0 += p00 + p01; ps1 += p10 + p11;
            const int ch = nt >> 1, hi = nt & 1;
            pfr[ch][2*hi    ] = pk(p00, p01);
            pfr[ch][2*hi + 1] = pk(p10, p11);
        }
        ps0 += __shfl_xor_sync(0xffffffffu, ps0, 1);
        ps0 += __shfl_xor_sync(0xffffffffu, ps0, 2);
        ps1 += __shfl_xor_sync(0xffffffffu, ps1, 1);
        ps1 += __shfl_xor_sync(0xffffffffu, ps1, 2);
        l0 = l0 * corr0 + ps0;
        l1 = l1 * corr1 + ps1;
        #pragma unroll
        for (int nt = 0; nt < 8; nt++){
            acc[nt][0] *= corr0; acc[nt][1] *= corr0;
            acc[nt][2] *= corr1; acc[nt][3] *= corr1;
        }

        // acc += P @ V. V B-frags via ldmatrix.trans on [t][d] rows:
        // matrices (k0-7,n0-7),(k8-15,n0-7),(k0-7,n8-15),(k8-15,n8-15) ->
        // regs {0,1} = n-tile 2j, {2,3} = n-tile 2j+1.
        #pragma unroll
        for (int ch = 0; ch < 4; ch++){
            const int tbase = ch * 16;
            #pragma unroll
            for (int j = 0; j < 4; j++){
                uint32_t bf[4];
                const int row = tbase + vt_k;
                const int cchunk = (j*2 + vt_n) ^ (row & 7);
                ldsm4t(bf, Vu + row*128 + (cchunk << 4));
                mma16(acc[2*j  ], pfr[ch], bf);
                mma16(acc[2*j+1], pfr[ch], bf + 2);
            }
        }
    }

    const float i0 = 1.f / l0, i1 = 1.f / l1;
    const size_t mrow = (size_t)(b*T_SZ) + q0 + wrow;
    #pragma unroll
    for (int nt = 0; nt < 8; nt++){
        const int c = nt*8 + 2*tig;
        const int wc = (h*HD + c) >> 1;
        Yw[(mrow + gid    )*(C_SZ/2) + wc] = pk(acc[nt][0]*i0, acc[nt][1]*i0);
        Yw[(mrow + gid + 8)*(C_SZ/2) + wc] = pk(acc[nt][2]*i1, acc[nt][3]*i1);
    }
}

extern "C" void kernel_launch(void* const* d_in, const int* in_sizes, int n_in,
                              void* d_out, int out_size)
{
    const float* x  = (const float*)d_in[0];
    const float* Wq = (const float*)d_in[1];
    const float* bq = (const float*)d_in[2];
    const float* Wk = (const float*)d_in[3];
    const float* bk = (const float*)d_in[4];
    const float* Wv = (const float*)d_in[5];
    const float* bv = (const float*)d_in[6];
    const float* Wo = (const float*)d_in[7];
    const float* bo = (const float*)d_in[8];
    float* out = (float*)d_out;

    __half *xhp, *qp, *kp, *vp, *yhp; uint32_t *wtp;
    cudaGetSymbolAddress((void**)&xhp, g_xh);
    cudaGetSymbolAddress((void**)&wtp, g_wt);
    cudaGetSymbolAddress((void**)&qp,  g_qh);
    cudaGetSymbolAddress((void**)&kp,  g_kh);
    cudaGetSymbolAddress((void**)&vp,  g_vh);
    cudaGetSymbolAddress((void**)&yhp, g_yh);

    cudaFuncSetAttribute(lm_gemm<0>, cudaFuncAttributeMaxDynamicSharedMemorySize, GDYN);
    cudaFuncSetAttribute(lm_gemm<1>, cudaFuncAttributeMaxDynamicSharedMemorySize, GDYN);
    cudaFuncSetAttribute(flash_tc, cudaFuncAttributeMaxDynamicSharedMemorySize, FLASH_SMEM);

    prep_x<<<2048, 256>>>(x, (uint32_t*)xhp);
    prep_w<<<dim3(16, 16, 4), 256>>>(Wq, Wk, Wv, Wo, wtp);

    lm_gemm<0><<<dim3(24, 32), 256, GDYN>>>(xhp, wtp, bq, bk, bv,
                                            (void*)qp, (void*)kp, (void*)vp);

    flash_tc<<<dim3(T_SZ/64, NH, B_SZ), 128, FLASH_SMEM>>>(qp, kp, vp, (uint32_t*)yhp);

    lm_gemm<1><<<dim3(8, 32), 256, GDYN>>>(yhp, wtp, bo, nullptr, nullptr,
                                           (void*)out, nullptr, nullptr);
}

// round 13
// speedup vs baseline: 1.2953x; 1.1842x over previous
#include <cuda_runtime.h>
#include <cuda_fp16.h>
#include <math.h>
#include <stdint.h>

#define B_SZ 2
#define T_SZ 2048
#define C_SZ 1024
#define NH   16
#define HD   64
#define M_SZ (B_SZ*T_SZ)   // 4096
#define LOG2E 1.44269504f

// Scratch (static device globals: allowed; runtime allocation is not)
__device__ __align__(256) __half   g_xh[M_SZ*C_SZ];           // x as fp16 [m][k]
__device__ __align__(256) uint32_t g_wt[4*C_SZ*(C_SZ/2)];     // W^T fp16 [w][n][k2] words
__device__ __align__(256) __half   g_qh[B_SZ*NH*T_SZ*HD];     // [bh][t][d]
__device__ __align__(256) __half   g_kh[B_SZ*NH*T_SZ*HD];     // [bh][t][d]
__device__ __align__(256) __half   g_vh[B_SZ*NH*T_SZ*HD];     // [bh][t][d]
__device__ __align__(256) __half   g_yh[M_SZ*C_SZ];           // attention out fp16 [m][c]

// ---------------------------------------------------------------------------
// helpers
// ---------------------------------------------------------------------------
__device__ __forceinline__ uint32_t pk(float lo, float hi){
    uint32_t r; asm("cvt.rn.f16x2.f32 %0, %1, %2;" : "=r"(r) : "f"(hi), "f"(lo));
    return r;
}
__device__ __forceinline__ uint32_t smem_u32(const void* p){
    uint32_t a;
    asm("{ .reg .u64 t; cvta.to.shared.u64 t, %1; cvt.u32.u64 %0, t; }"
        : "=r"(a) : "l"(p));
    return a;
}

#define CP16(dst, src) \
    asm volatile("cp.async.cg.shared.global [%0], [%1], 16;" \
                 :: "r"(dst), "l"(src) : "memory")
#define CP_COMMIT()  asm volatile("cp.async.commit_group;" ::: "memory")
#define CP_WAIT0()   asm volatile("cp.async.wait_group 0;" ::: "memory")
#define CP_WAIT1()   asm volatile("cp.async.wait_group 1;" ::: "memory")

// m16n8k16 fp16 mma, fp32 accumulate, D += A*B (C aliased to D)
__device__ __forceinline__ void mma16(float* d, const uint32_t* a, const uint32_t* b){
    asm volatile("mma.sync.aligned.m16n8k16.row.col.f32.f16.f16.f32 "
        "{%0,%1,%2,%3}, {%4,%5,%6,%7}, {%8,%9}, {%0,%1,%2,%3};"
        : "+f"(d[0]), "+f"(d[1]), "+f"(d[2]), "+f"(d[3])
        : "r"(a[0]), "r"(a[1]), "r"(a[2]), "r"(a[3]), "r"(b[0]), "r"(b[1]));
}

__device__ __forceinline__ void ldsm4(uint32_t* r, uint32_t saddr){
    asm volatile("ldmatrix.sync.aligned.m8n8.x4.shared.b16 {%0,%1,%2,%3}, [%4];"
        : "=r"(r[0]), "=r"(r[1]), "=r"(r[2]), "=r"(r[3]) : "r"(saddr));
}
__device__ __forceinline__ void ldsm4t(uint32_t* r, uint32_t saddr){
    asm volatile("ldmatrix.sync.aligned.m8n8.x4.trans.shared.b16 {%0,%1,%2,%3}, [%4];"
        : "=r"(r[0]), "=r"(r[1]), "=r"(r[2]), "=r"(r[3]) : "r"(saddr));
}

// ---------------------------------------------------------------------------
// prep kernels: x -> fp16 [m][k]; W[k][n] fp32 -> W^T [n][k] fp16 words
// ---------------------------------------------------------------------------
__global__ void prep_x(const float* __restrict__ x, uint32_t* __restrict__ xh){
    const int i = blockIdx.x * blockDim.x + threadIdx.x;
    #pragma unroll
    for (int p = 0; p < 4; p++){
        float2 v = ((const float2*)x)[i + p*524288];
        xh[i + p*524288] = pk(v.x, v.y);
    }
}

__global__ void prep_w(const float* __restrict__ Wq, const float* __restrict__ Wk,
                       const float* __restrict__ Wv, const float* __restrict__ Wo,
                       uint32_t* __restrict__ Wt){
    __shared__ float s[64][65];
    const int wsel = blockIdx.z;
    const float* W = (wsel==0)?Wq:(wsel==1)?Wk:(wsel==2)?Wv:Wo;
    const int k0 = blockIdx.y*64, n0 = blockIdx.x*64;
    const int tid = threadIdx.x;
    #pragma unroll
    for (int p = 0; p < 16; p++){
        const int lin = tid + p*256, kk = lin >> 6, nn = lin & 63;
        s[kk][nn] = W[(size_t)(k0+kk)*C_SZ + n0 + nn];
    }
    __syncthreads();
    uint32_t* out = Wt + (size_t)wsel * C_SZ * (C_SZ/2);
    #pragma unroll
    for (int p = 0; p < 8; p++){
        const int lin = tid + p*256, nn = lin >> 5, k2 = lin & 31;
        out[(size_t)(n0+nn)*(C_SZ/2) + (k0 >> 1) + k2] = pk(s[2*k2][nn], s[2*k2+1][nn]);
    }
}

// ---------------------------------------------------------------------------
// fp16 ldmatrix GEMM: 128x128 tile, KC=64, 8 warps (4m x 2n), warp 32x64.
// 3-stage cp.async smem ring, 1 barrier per K-step, latency fully hidden.
// Swizzle<3,3,3>: 16B chunk c -> c ^ (row&7). MODE 0 = QKV, MODE 1 = O-proj.
// ---------------------------------------------------------------------------
#define MODE_PLAIN   0
#define MODE_HEADS   1
#define KC 64
#define GTILE 16384                 // 128 rows x 128 B
#define GDYN  (6*GTILE)             // A0 A1 A2 B0 B1 B2 = 96 KB

template<int MODE>
__global__ __launch_bounds__(256, 2)
void lm_gemm(const __half* __restrict__ Aall, const uint32_t* __restrict__ Wt,
             const float* __restrict__ b0, const float* __restrict__ b1,
             const float* __restrict__ b2,
             void* __restrict__ o0, void* __restrict__ o1, void* __restrict__ o2)
{
    extern __shared__ char dsm[];
    const uint32_t sm0 = smem_u32(dsm);

    const int tid  = threadIdx.x;
    const int warp = tid >> 5, lane = tid & 31;
    const int gid  = lane >> 2, tig = lane & 3;
    const int warpM = (warp & 3) * 32, warpN = (warp >> 2) * 64;

    int which, bn, bm; const float* bias; void* outv;
    if (MODE == 0){
        which = blockIdx.x >> 3;
        bn = (blockIdx.x & 7) * 128;
        bm = blockIdx.y * 128;
        bias = (which==0)?b0:(which==1)?b1:b2;
        outv = (which==0)?o0:(which==1)?o1:o2;
    } else {
        which = 3; bn = blockIdx.x * 128; bm = blockIdx.y * 128;
        bias = b0; outv = o0;
    }

    const int a_m  = lane & 15, a_kg = lane >> 4;
    const int b_n  = (lane & 7) + ((lane >> 4) << 3);
    const int b_kg = (lane >> 3) & 1;
    const int lrow = tid >> 3, lseg = tid & 7;

    const __half*   Ah = Aall + (size_t)bm * C_SZ;
    const uint32_t* Bw = Wt + ((size_t)which * C_SZ + bn) * (C_SZ/2);

    // cp.async loader: per thread 4 A-chunks + 4 B-chunks of 16B per tile
    auto LOAD = [&](int k0, int s){
        const uint32_t Au = sm0 + s*GTILE;
        const uint32_t Bu = sm0 + 3*GTILE + s*GTILE;
        #pragma unroll
        for (int p = 0; p < 4; p++){
            const int row = lrow + 32*p;
            const uint32_t off = (uint32_t)(row*8 + (lseg ^ (row & 7))) << 4;
            CP16(Au + off, Ah + (size_t)row*C_SZ + k0 + lseg*8);
            CP16(Bu + off, Bw + (size_t)row*(C_SZ/2) + (k0>>1) + lseg*4);
        }
        CP_COMMIT();
    };

    float acc[2][8][4];
    #pragma unroll
    for (int mt = 0; mt < 2; mt++)
        #pragma unroll
        for (int nt = 0; nt < 8; nt++)
            #pragma unroll
            for (int e = 0; e < 4; e++) acc[mt][nt][e] = 0.f;

    auto COMPUTE = [&](int s){
        const uint32_t Au = sm0 + s*GTILE;
        const uint32_t Bu = sm0 + 3*GTILE + s*GTILE;
        #pragma unroll
        for (int kw = 0; kw < KC; kw += 16){
            const int cb = kw >> 3;
            uint32_t a[2][4];
            #pragma unroll
            for (int mt = 0; mt < 2; mt++){
                const int row = warpM + mt*16 + a_m;
                ldsm4(a[mt], Au + row*128 + (((cb + a_kg) ^ (row & 7)) << 4));
            }
            #pragma unroll
            for (int j = 0; j < 4; j++){
                uint32_t bf[4];
                const int row = warpN + j*16 + b_n;
                ldsm4(bf, Bu + row*128 + (((cb + b_kg) ^ (row & 7)) << 4));
                mma16(acc[0][2*j  ], a[0], bf);
                mma16(acc[0][2*j+1], a[0], bf + 2);
                mma16(acc[1][2*j  ], a[1], bf);
                mma16(acc[1][2*j+1], a[1], bf + 2);
            }
        }
    };

    LOAD(0, 0);
    LOAD(KC, 1);
    for (int i = 0; i < 16; i++){
        CP_WAIT1();          // tile i complete (tile i+1 may remain in flight)
        __syncthreads();     // + all warps done reading the buffer we reuse next
        if (i + 2 < 16) LOAD((i+2)*KC, (i+2)%3);
        COMPUTE(i%3);
        __syncthreads();
    }

    #pragma unroll
    for (int mt = 0; mt < 2; mt++){
        #pragma unroll
        for (int nt = 0; nt < 8; nt++){
            const int r = bm + warpM + mt*16 + gid;
            const int c = bn + warpN + nt*8 + 2*tig;
            const float b0v = bias[c], b1v = bias[c+1];
            float2 v0 = make_float2(acc[mt][nt][0] + b0v, acc[mt][nt][1] + b1v);
            float2 v1 = make_float2(acc[mt][nt][2] + b0v, acc[mt][nt][3] + b1v);
            if (MODE == 1){
                float* out = (float*)outv;
                *(float2*)&out[(size_t)r * C_SZ + c]     = v0;
                *(float2*)&out[(size_t)(r+8) * C_SZ + c] = v1;
            } else {
                const int b = r >> 11, t = r & 2047;
                const int h = c >> 6,  d = c & 63;
                const int bh = b*NH + h;
                __half* out = (__half*)outv;
                *(uint32_t*)&out[((size_t)bh * T_SZ + t    ) * HD + d] = pk(v0.x, v0.y);
                *(uint32_t*)&out[((size_t)bh * T_SZ + t + 8) * HD + d] = pk(v1.x, v1.y);
            }
        }
    }
}

// ---------------------------------------------------------------------------
// Flash attention, fp16 mma, BQ=64, BK=64, P in registers, all fragments via
// ldmatrix, K/V double-buffered with cp.async (load of tile kt+1 overlaps
// compute of tile kt). exp2-domain softmax. smem = Q + 2x(K,V) = 40 KB.
// ---------------------------------------------------------------------------
#define FTILE 8192   // 64 rows x 128 B
#define FLASH_SMEM (5*FTILE)

__global__ __launch_bounds__(128, 4)
void flash_tc(const __half* __restrict__ Q, const __half* __restrict__ K,
              const __half* __restrict__ V, uint32_t* __restrict__ Yw)
{
    extern __shared__ char fsm[];
    const uint32_t Qu  = smem_u32(fsm);
    const uint32_t KV0 = Qu + FTILE;           // [K0][V0][K1][V1]

    const int tid  = threadIdx.x;
    const int warp = tid >> 5, lane = tid & 31;
    const int gid  = lane >> 2, tig = lane & 3;
    const int qt   = (int)gridDim.x - 1 - (int)blockIdx.x;   // heavy first
    const int h    = blockIdx.y, b = blockIdx.z;
    const int bh   = b * NH + h;
    const int q0   = qt * 64;
    const int wrow = warp * 16;
    const float slope2 = exp2f(-0.5f * (float)(h + 1)) * LOG2E;
    const float scale2 = 0.125f * LOG2E;

    // ldmatrix lane-constant coords
    const int a_m  = lane & 15, a_kg = lane >> 4;           // A-frag (Q)
    const int b_n  = (lane & 7) + ((lane >> 4) << 3);       // B-frag non-trans (K)
    const int b_kg = (lane >> 3) & 1;
    const int vt_k = (lane & 7) + (((lane >> 3) & 1) << 3); // B-frag trans (V)
    const int vt_n = (lane >> 4);

    const int lrow = tid >> 3, lseg = tid & 7;

    const __half* qb = Q + ((size_t)bh * T_SZ + q0) * HD;
    const __half* kb = K + (size_t)bh * T_SZ * HD;
    const __half* vb = V + (size_t)bh * T_SZ * HD;

    // cp.async loader for one K/V tile pair into buffer bf
    auto LOAD_KV = [&](int k0, int bf){
        const uint32_t Kd = KV0 + (uint32_t)bf * 2*FTILE;
        #pragma unroll
        for (int p = 0; p < 4; p++){
            const int row = lrow + 16*p;
            const uint32_t off = (uint32_t)(row*8 + (lseg ^ (row & 7))) << 4;
            CP16(Kd + off,         kb + (size_t)(k0 + row)*HD + lseg*8);
            CP16(Kd + FTILE + off, vb + (size_t)(k0 + row)*HD + lseg*8);
        }
        CP_COMMIT();
    };

    {   // Q tile: plain swizzled copy (published at first loop barrier)
        uint4* Qs = (uint4*)fsm;
        #pragma unroll
        for (int p = 0; p < 4; p++){
            const int row = lrow + 16*p;
            Qs[row*8 + (lseg ^ (row & 7))] = *(const uint4*)(qb + (size_t)row*HD + lseg*8);
        }
    }
    LOAD_KV(0, 0);

    float m0 = -1e30f, m1 = -1e30f, l0 = 0.f, l1 = 0.f;
    float acc[8][4] = {};

    const int nkt = qt + 1;
    for (int kt = 0; kt < nkt; kt++){
        const int k0 = kt * 64;
        const int bf = kt & 1;
        const uint32_t Ku = KV0 + (uint32_t)bf * 2*FTILE;
        const uint32_t Vu = Ku + FTILE;

        CP_WAIT0();          // tile kt arrived
        __syncthreads();     // + everyone done with the buffer we refill next
        if (kt + 1 < nkt) LOAD_KV(k0 + 64, bf ^ 1);

        // S = Q K^T : warp's 16 q-rows x 64 keys (4 k16 chunks)
        float s[8][4] = {};
        #pragma unroll
        for (int ch = 0; ch < 4; ch++){
            const int cb = ch * 2;
            uint32_t af[4];
            {
                const int row = wrow + a_m;
                ldsm4(af, Qu + row*128 + (((cb + a_kg) ^ (row & 7)) << 4));
            }
            #pragma unroll
            for (int j = 0; j < 4; j++){
                uint32_t bfr[4];
                const int row = j*16 + b_n;
                ldsm4(bfr, Ku + row*128 + (((cb + b_kg) ^ (row & 7)) << 4));
                mma16(s[2*j  ], af, bfr);
                mma16(s[2*j+1], af, bfr + 2);
            }
        }

        // log2-domain ALiBi + causal + online softmax (all in fragments)
        const bool diag = (kt == nkt - 1);
        const int qi0 = q0 + wrow + gid, qi1 = qi0 + 8;
        float mx0 = -1e30f, mx1 = -1e30f;
        #pragma unroll
        for (int nt = 0; nt < 8; nt++){
            #pragma unroll
            for (int e = 0; e < 2; e++){
                const int ki = k0 + nt*8 + 2*tig + e;
                float sv0 = fmaf(s[nt][e],   scale2, slope2 * (float)(ki - qi0));
                float sv1 = fmaf(s[nt][2+e], scale2, slope2 * (float)(ki - qi1));
                if (diag && ki > qi0) sv0 = -1e30f;
                if (diag && ki > qi1) sv1 = -1e30f;
                s[nt][e] = sv0; s[nt][2+e] = sv1;
                mx0 = fmaxf(mx0, sv0); mx1 = fmaxf(mx1, sv1);
            }
        }
        mx0 = fmaxf(mx0, __shfl_xor_sync(0xffffffffu, mx0, 1));
        mx0 = fmaxf(mx0, __shfl_xor_sync(0xffffffffu, mx0, 2));
        mx1 = fmaxf(mx1, __shfl_xor_sync(0xffffffffu, mx1, 1));
        mx1 = fmaxf(mx1, __shfl_xor_sync(0xffffffffu, mx1, 2));
        const float mn0 = fmaxf(m0, mx0), mn1 = fmaxf(m1, mx1);
        const float corr0 = exp2f(m0 - mn0), corr1 = exp2f(m1 - mn1);
        m0 = mn0; m1 = mn1;

        // exp + pack P into A-fragments (C-frag layout == A-frag layout)
        uint32_t pfr[4][4];
        float ps0 = 0.f, ps1 = 0.f;
        #pragma unroll
        for (int nt = 0; nt < 8; nt++){
            const float p00 = exp2f(s[nt][0] - mn0), p01 = exp2f(s[nt][1] - mn0);
            const float p10 = exp2f(s[nt][2] - mn1), p11 = exp2f(s[nt][3] - mn1);
            ps0 += p00 + p01; ps1 += p10 + p11;
            const int ch = nt >> 1, hi = nt & 1;
            pfr[ch][2*hi    ] = pk(p00, p01);
            pfr[ch][2*hi + 1] = pk(p10, p11);
        }
        ps0 += __shfl_xor_sync(0xffffffffu, ps0, 1);
        ps0 += __shfl_xor_sync(0xffffffffu, ps0, 2);
        ps1 += __shfl_xor_sync(0xffffffffu, ps1, 1);
        ps1 += __shfl_xor_sync(0xffffffffu, ps1, 2);
        l0 = l0 * corr0 + ps0;
        l1 = l1 * corr1 + ps1;
        #pragma unroll
        for (int nt = 0; nt < 8; nt++){
            acc[nt][0] *= corr0; acc[nt][1] *= corr0;
            acc[nt][2] *= corr1; acc[nt][3] *= corr1;
        }

        // acc += P @ V (V B-frags via ldmatrix.trans on [t][d] rows)
        #pragma unroll
        for (int ch = 0; ch < 4; ch++){
            const int tbase = ch * 16;
            #pragma unroll
            for (int j = 0; j < 4; j++){
                uint32_t bfr[4];
                const int row = tbase + vt_k;
                const int cchunk = (j*2 + vt_n) ^ (row & 7);
                ldsm4t(bfr, Vu + row*128 + (cchunk << 4));
                mma16(acc[2*j  ], pfr[ch], bfr);
                mma16(acc[2*j+1], pfr[ch], bfr + 2);
            }
        }
    }

    const float i0 = 1.f / l0, i1 = 1.f / l1;
    const size_t mrow = (size_t)(b*T_SZ) + q0 + wrow;
    #pragma unroll
    for (int nt = 0; nt < 8; nt++){
        const int c = nt*8 + 2*tig;
        const int wc = (h*HD + c) >> 1;
        Yw[(mrow + gid    )*(C_SZ/2) + wc] = pk(acc[nt][0]*i0, acc[nt][1]*i0);
        Yw[(mrow + gid + 8)*(C_SZ/2) + wc] = pk(acc[nt][2]*i1, acc[nt][3]*i1);
    }
}

extern "C" void kernel_launch(void* const* d_in, const int* in_sizes, int n_in,
                              void* d_out, int out_size)
{
    const float* x  = (const float*)d_in[0];
    const float* Wq = (const float*)d_in[1];
    const float* bq = (const float*)d_in[2];
    const float* Wk = (const float*)d_in[3];
    const float* bk = (const float*)d_in[4];
    const float* Wv = (const float*)d_in[5];
    const float* bv = (const float*)d_in[6];
    const float* Wo = (const float*)d_in[7];
    const float* bo = (const float*)d_in[8];
    float* out = (float*)d_out;

    __half *xhp, *qp, *kp, *vp, *yhp; uint32_t *wtp;
    cudaGetSymbolAddress((void**)&xhp, g_xh);
    cudaGetSymbolAddress((void**)&wtp, g_wt);
    cudaGetSymbolAddress((void**)&qp,  g_qh);
    cudaGetSymbolAddress((void**)&kp,  g_kh);
    cudaGetSymbolAddress((void**)&vp,  g_vh);
    cudaGetSymbolAddress((void**)&yhp, g_yh);

    cudaFuncSetAttribute(lm_gemm<0>, cudaFuncAttributeMaxDynamicSharedMemorySize, GDYN);
    cudaFuncSetAttribute(lm_gemm<1>, cudaFuncAttributeMaxDynamicSharedMemorySize, GDYN);
    cudaFuncSetAttribute(flash_tc, cudaFuncAttributeMaxDynamicSharedMemorySize, FLASH_SMEM);

    prep_x<<<2048, 256>>>(x, (uint32_t*)xhp);
    prep_w<<<dim3(16, 16, 4), 256>>>(Wq, Wk, Wv, Wo, wtp);

    lm_gemm<0><<<dim3(24, 32), 256, GDYN>>>(xhp, wtp, bq, bk, bv,
                                            (void*)qp, (void*)kp, (void*)vp);

    flash_tc<<<dim3(T_SZ/64, NH, B_SZ), 128, FLASH_SMEM>>>(qp, kp, vp, (uint32_t*)yhp);

    lm_gemm<1><<<dim3(8, 32), 256, GDYN>>>(yhp, wtp, bo, nullptr, nullptr,
                                           (void*)out, nullptr, nullptr);
}

// round 14
// speedup vs baseline: 1.3631x; 1.0523x over previous
#include <cuda_runtime.h>
#include <cuda_fp16.h>
#include <math.h>
#include <stdint.h>

#define B_SZ 2
#define T_SZ 2048
#define C_SZ 1024
#define NH   16
#define HD   64
#define M_SZ (B_SZ*T_SZ)   // 4096
#define LOG2E 1.44269504f

// Scratch (static device globals: allowed; runtime allocation is not)
__device__ __align__(256) __half   g_xh[M_SZ*C_SZ];           // x as fp16 [m][k]
__device__ __align__(256) uint32_t g_wt[4*C_SZ*(C_SZ/2)];     // W^T fp16 [w][n][k2] words
__device__ __align__(256) __half   g_qh[B_SZ*NH*T_SZ*HD];     // [bh][t][d]
__device__ __align__(256) __half   g_kh[B_SZ*NH*T_SZ*HD];     // [bh][t][d]
__device__ __align__(256) __half   g_vh[B_SZ*NH*T_SZ*HD];     // [bh][t][d]
__device__ __align__(256) __half   g_yh[M_SZ*C_SZ];           // attention out fp16 [m][c]

// ---------------------------------------------------------------------------
// helpers
// ---------------------------------------------------------------------------
__device__ __forceinline__ uint32_t pk(float lo, float hi){
    uint32_t r; asm("cvt.rn.f16x2.f32 %0, %1, %2;" : "=r"(r) : "f"(hi), "f"(lo));
    return r;
}
__device__ __forceinline__ uint32_t smem_u32(const void* p){
    uint32_t a;
    asm("{ .reg .u64 t; cvta.to.shared.u64 t, %1; cvt.u32.u64 %0, t; }"
        : "=r"(a) : "l"(p));
    return a;
}

#define CP16(dst, src) \
    asm volatile("cp.async.cg.shared.global [%0], [%1], 16;" \
                 :: "r"(dst), "l"(src) : "memory")
#define CP_COMMIT()  asm volatile("cp.async.commit_group;" ::: "memory")
#define CP_WAIT0()   asm volatile("cp.async.wait_group 0;" ::: "memory")
#define CP_WAIT1()   asm volatile("cp.async.wait_group 1;" ::: "memory")

// m16n8k16 fp16 mma, fp32 accumulate, D += A*B (C aliased to D)
__device__ __forceinline__ void mma16(float* d, const uint32_t* a, const uint32_t* b){
    asm volatile("mma.sync.aligned.m16n8k16.row.col.f32.f16.f16.f32 "
        "{%0,%1,%2,%3}, {%4,%5,%6,%7}, {%8,%9}, {%0,%1,%2,%3};"
        : "+f"(d[0]), "+f"(d[1]), "+f"(d[2]), "+f"(d[3])
        : "r"(a[0]), "r"(a[1]), "r"(a[2]), "r"(a[3]), "r"(b[0]), "r"(b[1]));
}

__device__ __forceinline__ void ldsm4(uint32_t* r, uint32_t saddr){
    asm volatile("ldmatrix.sync.aligned.m8n8.x4.shared.b16 {%0,%1,%2,%3}, [%4];"
        : "=r"(r[0]), "=r"(r[1]), "=r"(r[2]), "=r"(r[3]) : "r"(saddr));
}
__device__ __forceinline__ void ldsm4t(uint32_t* r, uint32_t saddr){
    asm volatile("ldmatrix.sync.aligned.m8n8.x4.trans.shared.b16 {%0,%1,%2,%3}, [%4];"
        : "=r"(r[0]), "=r"(r[1]), "=r"(r[2]), "=r"(r[3]) : "r"(saddr));
}

// ---------------------------------------------------------------------------
// prep kernels: x -> fp16 [m][k]; W[k][n] fp32 -> W^T [n][k] fp16 words
// ---------------------------------------------------------------------------
__global__ void prep_x(const float* __restrict__ x, uint32_t* __restrict__ xh){
    const int i = blockIdx.x * blockDim.x + threadIdx.x;
    #pragma unroll
    for (int p = 0; p < 4; p++){
        float2 v = ((const float2*)x)[i + p*524288];
        xh[i + p*524288] = pk(v.x, v.y);
    }
}

__global__ void prep_w(const float* __restrict__ Wq, const float* __restrict__ Wk,
                       const float* __restrict__ Wv, const float* __restrict__ Wo,
                       uint32_t* __restrict__ Wt){
    __shared__ float s[64][65];
    const int wsel = blockIdx.z;
    const float* W = (wsel==0)?Wq:(wsel==1)?Wk:(wsel==2)?Wv:Wo;
    const int k0 = blockIdx.y*64, n0 = blockIdx.x*64;
    const int tid = threadIdx.x;
    #pragma unroll
    for (int p = 0; p < 16; p++){
        const int lin = tid + p*256, kk = lin >> 6, nn = lin & 63;
        s[kk][nn] = W[(size_t)(k0+kk)*C_SZ + n0 + nn];
    }
    __syncthreads();
    uint32_t* out = Wt + (size_t)wsel * C_SZ * (C_SZ/2);
    #pragma unroll
    for (int p = 0; p < 8; p++){
        const int lin = tid + p*256, nn = lin >> 5, k2 = lin & 31;
        out[(size_t)(n0+nn)*(C_SZ/2) + (k0 >> 1) + k2] = pk(s[2*k2][nn], s[2*k2+1][nn]);
    }
}

// ---------------------------------------------------------------------------
// fp16 ldmatrix GEMM: 128x128 tile, KC=64, 8 warps (4m x 2n), warp 32x64.
// 3-stage cp.async smem ring, ONE barrier per K-step (top-of-iter barrier
// proves compute i-1 done before its buffer is re-issued).
// Swizzle<3,3,3>: 16B chunk c -> c ^ (row&7). MODE 0 = QKV, MODE 1 = O-proj.
// ---------------------------------------------------------------------------
#define MODE_PLAIN   0
#define MODE_HEADS   1
#define KC 64
#define GTILE 16384                 // 128 rows x 128 B
#define GDYN  (6*GTILE)             // A0 A1 A2 B0 B1 B2 = 96 KB

template<int MODE>
__global__ __launch_bounds__(256, 2)
void lm_gemm(const __half* __restrict__ Aall, const uint32_t* __restrict__ Wt,
             const float* __restrict__ b0, const float* __restrict__ b1,
             const float* __restrict__ b2,
             void* __restrict__ o0, void* __restrict__ o1, void* __restrict__ o2)
{
    extern __shared__ char dsm[];
    const uint32_t sm0 = smem_u32(dsm);

    const int tid  = threadIdx.x;
    const int warp = tid >> 5, lane = tid & 31;
    const int gid  = lane >> 2, tig = lane & 3;
    const int warpM = (warp & 3) * 32, warpN = (warp >> 2) * 64;

    int which, bn, bm; const float* bias; void* outv;
    if (MODE == 0){
        which = blockIdx.x >> 3;
        bn = (blockIdx.x & 7) * 128;
        bm = blockIdx.y * 128;
        bias = (which==0)?b0:(which==1)?b1:b2;
        outv = (which==0)?o0:(which==1)?o1:o2;
    } else {
        which = 3; bn = blockIdx.x * 128; bm = blockIdx.y * 128;
        bias = b0; outv = o0;
    }

    const int a_m  = lane & 15, a_kg = lane >> 4;
    const int b_n  = (lane & 7) + ((lane >> 4) << 3);
    const int b_kg = (lane >> 3) & 1;
    const int lrow = tid >> 3, lseg = tid & 7;

    const __half*   Ah = Aall + (size_t)bm * C_SZ;
    const uint32_t* Bw = Wt + ((size_t)which * C_SZ + bn) * (C_SZ/2);

    auto LOAD = [&](int k0, int s){
        const uint32_t Au = sm0 + s*GTILE;
        const uint32_t Bu = sm0 + 3*GTILE + s*GTILE;
        #pragma unroll
        for (int p = 0; p < 4; p++){
            const int row = lrow + 32*p;
            const uint32_t off = (uint32_t)(row*8 + (lseg ^ (row & 7))) << 4;
            CP16(Au + off, Ah + (size_t)row*C_SZ + k0 + lseg*8);
            CP16(Bu + off, Bw + (size_t)row*(C_SZ/2) + (k0>>1) + lseg*4);
        }
        CP_COMMIT();
    };

    float acc[2][8][4];
    #pragma unroll
    for (int mt = 0; mt < 2; mt++)
        #pragma unroll
        for (int nt = 0; nt < 8; nt++)
            #pragma unroll
            for (int e = 0; e < 4; e++) acc[mt][nt][e] = 0.f;

    auto COMPUTE = [&](int s){
        const uint32_t Au = sm0 + s*GTILE;
        const uint32_t Bu = sm0 + 3*GTILE + s*GTILE;
        #pragma unroll
        for (int kw = 0; kw < KC; kw += 16){
            const int cb = kw >> 3;
            uint32_t a[2][4];
            #pragma unroll
            for (int mt = 0; mt < 2; mt++){
                const int row = warpM + mt*16 + a_m;
                ldsm4(a[mt], Au + row*128 + (((cb + a_kg) ^ (row & 7)) << 4));
            }
            #pragma unroll
            for (int j = 0; j < 4; j++){
                uint32_t bf[4];
                const int row = warpN + j*16 + b_n;
                ldsm4(bf, Bu + row*128 + (((cb + b_kg) ^ (row & 7)) << 4));
                mma16(acc[0][2*j  ], a[0], bf);
                mma16(acc[0][2*j+1], a[0], bf + 2);
                mma16(acc[1][2*j  ], a[1], bf);
                mma16(acc[1][2*j+1], a[1], bf + 2);
            }
        }
    };

    LOAD(0, 0);
    LOAD(KC, 1);
    for (int i = 0; i < 16; i++){
        CP_WAIT1();          // tile i complete (tile i+1 may remain in flight)
        __syncthreads();     // all warps finished compute i-1 (buffer reuse safe)
        if (i + 2 < 16) LOAD((i+2)*KC, (i+2)%3);
        COMPUTE(i%3);
    }

    #pragma unroll
    for (int mt = 0; mt < 2; mt++){
        #pragma unroll
        for (int nt = 0; nt < 8; nt++){
            const int r = bm + warpM + mt*16 + gid;
            const int c = bn + warpN + nt*8 + 2*tig;
            const float b0v = bias[c], b1v = bias[c+1];
            float2 v0 = make_float2(acc[mt][nt][0] + b0v, acc[mt][nt][1] + b1v);
            float2 v1 = make_float2(acc[mt][nt][2] + b0v, acc[mt][nt][3] + b1v);
            if (MODE == 1){
                float* out = (float*)outv;
                *(float2*)&out[(size_t)r * C_SZ + c]     = v0;
                *(float2*)&out[(size_t)(r+8) * C_SZ + c] = v1;
            } else {
                const int b = r >> 11, t = r & 2047;
                const int h = c >> 6,  d = c & 63;
                const int bh = b*NH + h;
                __half* out = (__half*)outv;
                *(uint32_t*)&out[((size_t)bh * T_SZ + t    ) * HD + d] = pk(v0.x, v0.y);
                *(uint32_t*)&out[((size_t)bh * T_SZ + t + 8) * HD + d] = pk(v1.x, v1.y);
            }
        }
    }
}

// ---------------------------------------------------------------------------
// Flash attention, fp16 mma, BQ=64, BK=64, P in registers, ldmatrix frags,
// cp.async double-buffered K/V. REVERSE K-order (diagonal tile first):
//  - masked (causal) code peeled into the first tile only
//  - running max rarely changes after tile 1 -> warp-vote skips acc rescale
//  - ALiBi bias strength-reduced to FFMA-imm chains
// ---------------------------------------------------------------------------
#define FTILE 8192   // 64 rows x 128 B
#define FLASH_SMEM (5*FTILE)

__global__ __launch_bounds__(128, 4)
void flash_tc(const __half* __restrict__ Q, const __half* __restrict__ K,
              const __half* __restrict__ V, uint32_t* __restrict__ Yw)
{
    extern __shared__ char fsm[];
    const uint32_t Qu  = smem_u32(fsm);
    const uint32_t KV0 = Qu + FTILE;           // [K0][V0][K1][V1]

    const int tid  = threadIdx.x;
    const int warp = tid >> 5, lane = tid & 31;
    const int gid  = lane >> 2, tig = lane & 3;
    const int qt   = (int)gridDim.x - 1 - (int)blockIdx.x;   // heavy first
    const int h    = blockIdx.y, b = blockIdx.z;
    const int bh   = b * NH + h;
    const int q0   = qt * 64;
    const int wrow = warp * 16;
    const float slope2 = exp2f(-0.5f * (float)(h + 1)) * LOG2E;
    const float scale2 = 0.125f * LOG2E;

    const int a_m  = lane & 15, a_kg = lane >> 4;           // A-frag (Q)
    const int b_n  = (lane & 7) + ((lane >> 4) << 3);       // B-frag non-trans (K)
    const int b_kg = (lane >> 3) & 1;
    const int vt_k = (lane & 7) + (((lane >> 3) & 1) << 3); // B-frag trans (V)
    const int vt_n = (lane >> 4);

    const int lrow = tid >> 3, lseg = tid & 7;

    const __half* qb = Q + ((size_t)bh * T_SZ + q0) * HD;
    const __half* kb = K + (size_t)bh * T_SZ * HD;
    const __half* vb = V + (size_t)bh * T_SZ * HD;

    auto LOAD_KV = [&](int k0, int bf){
        const uint32_t Kd = KV0 + (uint32_t)bf * 2*FTILE;
        #pragma unroll
        for (int p = 0; p < 4; p++){
            const int row = lrow + 16*p;
            const uint32_t off = (uint32_t)(row*8 + (lseg ^ (row & 7))) << 4;
            CP16(Kd + off,         kb + (size_t)(k0 + row)*HD + lseg*8);
            CP16(Kd + FTILE + off, vb + (size_t)(k0 + row)*HD + lseg*8);
        }
        CP_COMMIT();
    };

    {   // Q tile: plain swizzled copy (published at first loop barrier)
        uint4* Qs = (uint4*)fsm;
        #pragma unroll
        for (int p = 0; p < 4; p++){
            const int row = lrow + 16*p;
            Qs[row*8 + (lseg ^ (row & 7))] = *(const uint4*)(qb + (size_t)row*HD + lseg*8);
        }
    }

    float m0 = -1e30f, m1 = -1e30f, l0 = 0.f, l1 = 0.f;
    float acc[8][4] = {};

    const int qi0 = q0 + wrow + gid, qi1 = qi0 + 8;

    // per-tile body; diag folds at inlined call sites
    auto BODY = [&](int k0, int bf, bool diag){
        const uint32_t Ku = KV0 + (uint32_t)bf * 2*FTILE;
        const uint32_t Vu = Ku + FTILE;

        // S = Q K^T
        float s[8][4] = {};
        #pragma unroll
        for (int ch = 0; ch < 4; ch++){
            const int cb = ch * 2;
            uint32_t af[4];
            {
                const int row = wrow + a_m;
                ldsm4(af, Qu + row*128 + (((cb + a_kg) ^ (row & 7)) << 4));
            }
            #pragma unroll
            for (int j = 0; j < 4; j++){
                uint32_t bfr[4];
                const int row = j*16 + b_n;
                ldsm4(bfr, Ku + row*128 + (((cb + b_kg) ^ (row & 7)) << 4));
                mma16(s[2*j  ], af, bfr);
                mma16(s[2*j+1], af, bfr + 2);
            }
        }

        // ALiBi (strength-reduced) + optional causal mask + online softmax
        const float bb0 = slope2 * (float)(k0 + 2*tig - qi0);
        const float bb1 = slope2 * (float)(k0 + 2*tig - qi1);
        float mx0 = -1e30f, mx1 = -1e30f;
        #pragma unroll
        for (int nt = 0; nt < 8; nt++){
            #pragma unroll
            for (int e = 0; e < 2; e++){
                const float cf = (float)(nt*8 + e);
                float sv0 = fmaf(s[nt][e],   scale2, fmaf(cf, slope2, bb0));
                float sv1 = fmaf(s[nt][2+e], scale2, fmaf(cf, slope2, bb1));
                if (diag){
                    const int ki = k0 + nt*8 + 2*tig + e;
                    if (ki > qi0) sv0 = -1e30f;
                    if (ki > qi1) sv1 = -1e30f;
                }
                s[nt][e] = sv0; s[nt][2+e] = sv1;
                mx0 = fmaxf(mx0, sv0); mx1 = fmaxf(mx1, sv1);
            }
        }
        mx0 = fmaxf(mx0, __shfl_xor_sync(0xffffffffu, mx0, 1));
        mx0 = fmaxf(mx0, __shfl_xor_sync(0xffffffffu, mx0, 2));
        mx1 = fmaxf(mx1, __shfl_xor_sync(0xffffffffu, mx1, 1));
        mx1 = fmaxf(mx1, __shfl_xor_sync(0xffffffffu, mx1, 2));
        const float mn0 = fmaxf(m0, mx0), mn1 = fmaxf(m1, mx1);

        // warp-vote: skip rescale when max unchanged for ALL lanes (corr==1)
        const bool nochg = (mn0 == m0) && (mn1 == m1);
        if (!__all_sync(0xffffffffu, nochg)){
            const float corr0 = exp2f(m0 - mn0), corr1 = exp2f(m1 - mn1);
            l0 *= corr0; l1 *= corr1;
            #pragma unroll
            for (int nt = 0; nt < 8; nt++){
                acc[nt][0] *= corr0; acc[nt][1] *= corr0;
                acc[nt][2] *= corr1; acc[nt][3] *= corr1;
            }
        }
        m0 = mn0; m1 = mn1;

        // exp + pack P into A-fragments (C-frag layout == A-frag layout)
        uint32_t pfr[4][4];
        float ps0 = 0.f, ps1 = 0.f;
        #pragma unroll
        for (int nt = 0; nt < 8; nt++){
            const float p00 = exp2f(s[nt][0] - m0), p01 = exp2f(s[nt][1] - m0);
            const float p10 = exp2f(s[nt][2] - m1), p11 = exp2f(s[nt][3] - m1);
            ps0 += p00 + p01; ps1 += p10 + p11;
            const int ch = nt >> 1, hi = nt & 1;
            pfr[ch][2*hi    ] = pk(p00, p01);
            pfr[ch][2*hi + 1] = pk(p10, p11);
        }
        ps0 += __shfl_xor_sync(0xffffffffu, ps0, 1);
        ps0 += __shfl_xor_sync(0xffffffffu, ps0, 2);
        ps1 += __shfl_xor_sync(0xffffffffu, ps1, 1);
        ps1 += __shfl_xor_sync(0xffffffffu, ps1, 2);
        l0 += ps0;
        l1 += ps1;

        // acc += P @ V (V B-frags via ldmatrix.trans on [t][d] rows)
        #pragma unroll
        for (int ch = 0; ch < 4; ch++){
            const int tbase = ch * 16;
            #pragma unroll
            for (int j = 0; j < 4; j++){
                uint32_t bfr[4];
                const int row = tbase + vt_k;
                const int cchunk = (j*2 + vt_n) ^ (row & 7);
                ldsm4t(bfr, Vu + row*128 + (cchunk << 4));
                mma16(acc[2*j  ], pfr[ch], bfr);
                mma16(acc[2*j+1], pfr[ch], bfr + 2);
            }
        }
    };

    const int nkt = qt + 1;
    LOAD_KV((nkt-1)*64, (nkt-1)&1);     // diagonal tile first

    {   // peeled diagonal (masked) tile
        CP_WAIT0();
        __syncthreads();
        if (nkt > 1) LOAD_KV((nkt-2)*64, (nkt-2)&1);
        BODY((nkt-1)*64, (nkt-1)&1, true);
    }
    for (int kt = nkt-2; kt >= 0; kt--){   // mask-free tiles, descending
        CP_WAIT0();
        __syncthreads();
        if (kt > 0) LOAD_KV((kt-1)*64, (kt-1)&1);
        BODY(kt*64, kt&1, false);
    }

    const float i0 = 1.f / l0, i1 = 1.f / l1;
    const size_t mrow = (size_t)(b*T_SZ) + q0 + wrow;
    #pragma unroll
    for (int nt = 0; nt < 8; nt++){
        const int c = nt*8 + 2*tig;
        const int wc = (h*HD + c) >> 1;
        Yw[(mrow + gid    )*(C_SZ/2) + wc] = pk(acc[nt][0]*i0, acc[nt][1]*i0);
        Yw[(mrow + gid + 8)*(C_SZ/2) + wc] = pk(acc[nt][2]*i1, acc[nt][3]*i1);
    }
}

extern "C" void kernel_launch(void* const* d_in, const int* in_sizes, int n_in,
                              void* d_out, int out_size)
{
    const float* x  = (const float*)d_in[0];
    const float* Wq = (const float*)d_in[1];
    const float* bq = (const float*)d_in[2];
    const float* Wk = (const float*)d_in[3];
    const float* bk = (const float*)d_in[4];
    const float* Wv = (const float*)d_in[5];
    const float* bv = (const float*)d_in[6];
    const float* Wo = (const float*)d_in[7];
    const float* bo = (const float*)d_in[8];
    float* out = (float*)d_out;

    __half *xhp, *qp, *kp, *vp, *yhp; uint32_t *wtp;
    cudaGetSymbolAddress((void**)&xhp, g_xh);
    cudaGetSymbolAddress((void**)&wtp, g_wt);
    cudaGetSymbolAddress((void**)&qp,  g_qh);
    cudaGetSymbolAddress((void**)&kp,  g_kh);
    cudaGetSymbolAddress((void**)&vp,  g_vh);
    cudaGetSymbolAddress((void**)&yhp, g_yh);

    cudaFuncSetAttribute(lm_gemm<0>, cudaFuncAttributeMaxDynamicSharedMemorySize, GDYN);
    cudaFuncSetAttribute(lm_gemm<1>, cudaFuncAttributeMaxDynamicSharedMemorySize, GDYN);
    cudaFuncSetAttribute(flash_tc, cudaFuncAttributeMaxDynamicSharedMemorySize, FLASH_SMEM);

    prep_x<<<2048, 256>>>(x, (uint32_t*)xhp);
    prep_w<<<dim3(16, 16, 4), 256>>>(Wq, Wk, Wv, Wo, wtp);

    lm_gemm<0><<<dim3(24, 32), 256, GDYN>>>(xhp, wtp, bq, bk, bv,
                                            (void*)qp, (void*)kp, (void*)vp);

    flash_tc<<<dim3(T_SZ/64, NH, B_SZ), 128, FLASH_SMEM>>>(qp, kp, vp, (uint32_t*)yhp);

    lm_gemm<1><<<dim3(8, 32), 256, GDYN>>>(yhp, wtp, bo, nullptr, nullptr,
                                           (void*)out, nullptr, nullptr);
}

// round 15
// speedup vs baseline: 1.4065x; 1.0319x over previous
#include <cuda_runtime.h>
#include <cuda_fp16.h>
#include <math.h>
#include <stdint.h>

#define B_SZ 2
#define T_SZ 2048
#define C_SZ 1024
#define NH   16
#define HD   64
#define M_SZ (B_SZ*T_SZ)   // 4096
#define LOG2E 1.44269504f

// Scratch (static device globals: allowed; runtime allocation is not)
__device__ __align__(256) __half   g_xh[M_SZ*C_SZ];           // x as fp16 [m][k]
__device__ __align__(256) uint32_t g_wt[4*C_SZ*(C_SZ/2)];     // W^T fp16 [w][n][k2] words
__device__ __align__(256) __half   g_qh[B_SZ*NH*T_SZ*HD];     // [bh][t][d]
__device__ __align__(256) __half   g_kh[B_SZ*NH*T_SZ*HD];     // [bh][t][d]
__device__ __align__(256) __half   g_vh[B_SZ*NH*T_SZ*HD];     // [bh][t][d]
__device__ __align__(256) __half   g_yh[M_SZ*C_SZ];           // attention out fp16 [m][c]

// ---------------------------------------------------------------------------
// helpers
// ---------------------------------------------------------------------------
__device__ __forceinline__ uint32_t pk(float lo, float hi){
    uint32_t r; asm("cvt.rn.f16x2.f32 %0, %1, %2;" : "=r"(r) : "f"(hi), "f"(lo));
    return r;
}
__device__ __forceinline__ uint32_t ex2h2(uint32_t x){
    uint32_t r; asm("ex2.approx.f16x2 %0, %1;" : "=r"(r) : "r"(x));
    return r;
}
__device__ __forceinline__ uint32_t smem_u32(const void* p){
    uint32_t a;
    asm("{ .reg .u64 t; cvta.to.shared.u64 t, %1; cvt.u32.u64 %0, t; }"
        : "=r"(a) : "l"(p));
    return a;
}

#define CP16(dst, src) \
    asm volatile("cp.async.cg.shared.global [%0], [%1], 16;" \
                 :: "r"(dst), "l"(src) : "memory")
#define CP_COMMIT()  asm volatile("cp.async.commit_group;" ::: "memory")
#define CP_WAIT0()   asm volatile("cp.async.wait_group 0;" ::: "memory")
#define CP_WAIT1()   asm volatile("cp.async.wait_group 1;" ::: "memory")

// m16n8k16 fp16 mma, fp32 accumulate, D += A*B (C aliased to D)
__device__ __forceinline__ void mma16(float* d, const uint32_t* a, const uint32_t* b){
    asm volatile("mma.sync.aligned.m16n8k16.row.col.f32.f16.f16.f32 "
        "{%0,%1,%2,%3}, {%4,%5,%6,%7}, {%8,%9}, {%0,%1,%2,%3};"
        : "+f"(d[0]), "+f"(d[1]), "+f"(d[2]), "+f"(d[3])
        : "r"(a[0]), "r"(a[1]), "r"(a[2]), "r"(a[3]), "r"(b[0]), "r"(b[1]));
}

__device__ __forceinline__ void ldsm4(uint32_t* r, uint32_t saddr){
    asm volatile("ldmatrix.sync.aligned.m8n8.x4.shared.b16 {%0,%1,%2,%3}, [%4];"
        : "=r"(r[0]), "=r"(r[1]), "=r"(r[2]), "=r"(r[3]) : "r"(saddr));
}
__device__ __forceinline__ void ldsm4t(uint32_t* r, uint32_t saddr){
    asm volatile("ldmatrix.sync.aligned.m8n8.x4.trans.shared.b16 {%0,%1,%2,%3}, [%4];"
        : "=r"(r[0]), "=r"(r[1]), "=r"(r[2]), "=r"(r[3]) : "r"(saddr));
}

// ---------------------------------------------------------------------------
// prep kernels: x -> fp16 [m][k]; W[k][n] fp32 -> W^T [n][k] fp16 words
// ---------------------------------------------------------------------------
__global__ void prep_x(const float* __restrict__ x, uint32_t* __restrict__ xh){
    const int i = blockIdx.x * blockDim.x + threadIdx.x;
    #pragma unroll
    for (int p = 0; p < 4; p++){
        float2 v = ((const float2*)x)[i + p*524288];
        xh[i + p*524288] = pk(v.x, v.y);
    }
}

__global__ void prep_w(const float* __restrict__ Wq, const float* __restrict__ Wk,
                       const float* __restrict__ Wv, const float* __restrict__ Wo,
                       uint32_t* __restrict__ Wt){
    __shared__ float s[64][65];
    const int wsel = blockIdx.z;
    const float* W = (wsel==0)?Wq:(wsel==1)?Wk:(wsel==2)?Wv:Wo;
    const int k0 = blockIdx.y*64, n0 = blockIdx.x*64;
    const int tid = threadIdx.x;
    #pragma unroll
    for (int p = 0; p < 16; p++){
        const int lin = tid + p*256, kk = lin >> 6, nn = lin & 63;
        s[kk][nn] = W[(size_t)(k0+kk)*C_SZ + n0 + nn];
    }
    __syncthreads();
    uint32_t* out = Wt + (size_t)wsel * C_SZ * (C_SZ/2);
    #pragma unroll
    for (int p = 0; p < 8; p++){
        const int lin = tid + p*256, nn = lin >> 5, k2 = lin & 31;
        out[(size_t)(n0+nn)*(C_SZ/2) + (k0 >> 1) + k2] = pk(s[2*k2][nn], s[2*k2+1][nn]);
    }
}

// ---------------------------------------------------------------------------
// fp16 ldmatrix GEMM: 128x128 tile, KC=64, 8 warps (4m x 2n), warp 32x64.
// 3-stage cp.async smem ring, ONE barrier per K-step.
// Swizzle<3,3,3>: 16B chunk c -> c ^ (row&7). MODE 0 = QKV, MODE 1 = O-proj.
// ---------------------------------------------------------------------------
#define MODE_PLAIN   0
#define MODE_HEADS   1
#define KC 64
#define GTILE 16384                 // 128 rows x 128 B
#define GDYN  (6*GTILE)             // A0 A1 A2 B0 B1 B2 = 96 KB

template<int MODE>
__global__ __launch_bounds__(256, 2)
void lm_gemm(const __half* __restrict__ Aall, const uint32_t* __restrict__ Wt,
             const float* __restrict__ b0, const float* __restrict__ b1,
             const float* __restrict__ b2,
             void* __restrict__ o0, void* __restrict__ o1, void* __restrict__ o2)
{
    extern __shared__ char dsm[];
    const uint32_t sm0 = smem_u32(dsm);

    const int tid  = threadIdx.x;
    const int warp = tid >> 5, lane = tid & 31;
    const int gid  = lane >> 2, tig = lane & 3;
    const int warpM = (warp & 3) * 32, warpN = (warp >> 2) * 64;

    int which, bn, bm; const float* bias; void* outv;
    if (MODE == 0){
        which = blockIdx.x >> 3;
        bn = (blockIdx.x & 7) * 128;
        bm = blockIdx.y * 128;
        bias = (which==0)?b0:(which==1)?b1:b2;
        outv = (which==0)?o0:(which==1)?o1:o2;
    } else {
        which = 3; bn = blockIdx.x * 128; bm = blockIdx.y * 128;
        bias = b0; outv = o0;
    }

    const int a_m  = lane & 15, a_kg = lane >> 4;
    const int b_n  = (lane & 7) + ((lane >> 4) << 3);
    const int b_kg = (lane >> 3) & 1;
    const int lrow = tid >> 3, lseg = tid & 7;

    const __half*   Ah = Aall + (size_t)bm * C_SZ;
    const uint32_t* Bw = Wt + ((size_t)which * C_SZ + bn) * (C_SZ/2);

    auto LOAD = [&](int k0, int s){
        const uint32_t Au = sm0 + s*GTILE;
        const uint32_t Bu = sm0 + 3*GTILE + s*GTILE;
        #pragma unroll
        for (int p = 0; p < 4; p++){
            const int row = lrow + 32*p;
            const uint32_t off = (uint32_t)(row*8 + (lseg ^ (row & 7))) << 4;
            CP16(Au + off, Ah + (size_t)row*C_SZ + k0 + lseg*8);
            CP16(Bu + off, Bw + (size_t)row*(C_SZ/2) + (k0>>1) + lseg*4);
        }
        CP_COMMIT();
    };

    float acc[2][8][4];
    #pragma unroll
    for (int mt = 0; mt < 2; mt++)
        #pragma unroll
        for (int nt = 0; nt < 8; nt++)
            #pragma unroll
            for (int e = 0; e < 4; e++) acc[mt][nt][e] = 0.f;

    auto COMPUTE = [&](int s){
        const uint32_t Au = sm0 + s*GTILE;
        const uint32_t Bu = sm0 + 3*GTILE + s*GTILE;
        #pragma unroll
        for (int kw = 0; kw < KC; kw += 16){
            const int cb = kw >> 3;
            uint32_t a[2][4];
            #pragma unroll
            for (int mt = 0; mt < 2; mt++){
                const int row = warpM + mt*16 + a_m;
                ldsm4(a[mt], Au + row*128 + (((cb + a_kg) ^ (row & 7)) << 4));
            }
            #pragma unroll
            for (int j = 0; j < 4; j++){
                uint32_t bf[4];
                const int row = warpN + j*16 + b_n;
                ldsm4(bf, Bu + row*128 + (((cb + b_kg) ^ (row & 7)) << 4));
                mma16(acc[0][2*j  ], a[0], bf);
                mma16(acc[0][2*j+1], a[0], bf + 2);
                mma16(acc[1][2*j  ], a[1], bf);
                mma16(acc[1][2*j+1], a[1], bf + 2);
            }
        }
    };

    LOAD(0, 0);
    LOAD(KC, 1);
    for (int i = 0; i < 16; i++){
        CP_WAIT1();          // tile i complete (tile i+1 may remain in flight)
        __syncthreads();     // all warps finished compute i-1 (buffer reuse safe)
        if (i + 2 < 16) LOAD((i+2)*KC, (i+2)%3);
        COMPUTE(i%3);
    }

    #pragma unroll
    for (int mt = 0; mt < 2; mt++){
        #pragma unroll
        for (int nt = 0; nt < 8; nt++){
            const int r = bm + warpM + mt*16 + gid;
            const int c = bn + warpN + nt*8 + 2*tig;
            const float b0v = bias[c], b1v = bias[c+1];
            float2 v0 = make_float2(acc[mt][nt][0] + b0v, acc[mt][nt][1] + b1v);
            float2 v1 = make_float2(acc[mt][nt][2] + b0v, acc[mt][nt][3] + b1v);
            if (MODE == 1){
                float* out = (float*)outv;
                *(float2*)&out[(size_t)r * C_SZ + c]     = v0;
                *(float2*)&out[(size_t)(r+8) * C_SZ + c] = v1;
            } else {
                const int b = r >> 11, t = r & 2047;
                const int h = c >> 6,  d = c & 63;
                const int bh = b*NH + h;
                __half* out = (__half*)outv;
                *(uint32_t*)&out[((size_t)bh * T_SZ + t    ) * HD + d] = pk(v0.x, v0.y);
                *(uint32_t*)&out[((size_t)bh * T_SZ + t + 8) * HD + d] = pk(v1.x, v1.y);
            }
        }
    }
}

// ---------------------------------------------------------------------------
// Flash attention, fp16 mma, BQ=64, BK=64, P in registers, ldmatrix frags,
// cp.async double-buffered K/V, diagonal-first K order.
// R14: l computed by ones-mma (P @ 1, constant B-frag, exact fp32 row sums),
//      exp via ex2.approx.f16x2 (P emerges pre-packed, half the MUFU work).
// ---------------------------------------------------------------------------
#define FTILE 8192   // 64 rows x 128 B
#define FLASH_SMEM (5*FTILE)

__global__ __launch_bounds__(128, 4)
void flash_tc(const __half* __restrict__ Q, const __half* __restrict__ K,
              const __half* __restrict__ V, uint32_t* __restrict__ Yw)
{
    extern __shared__ char fsm[];
    const uint32_t Qu  = smem_u32(fsm);
    const uint32_t KV0 = Qu + FTILE;           // [K0][V0][K1][V1]

    const int tid  = threadIdx.x;
    const int warp = tid >> 5, lane = tid & 31;
    const int gid  = lane >> 2, tig = lane & 3;
    const int qt   = (int)gridDim.x - 1 - (int)blockIdx.x;   // heavy first
    const int h    = blockIdx.y, b = blockIdx.z;
    const int bh   = b * NH + h;
    const int q0   = qt * 64;
    const int wrow = warp * 16;
    const float slope2 = exp2f(-0.5f * (float)(h + 1)) * LOG2E;
    const float scale2 = 0.125f * LOG2E;

    const int a_m  = lane & 15, a_kg = lane >> 4;           // A-frag (Q)
    const int b_n  = (lane & 7) + ((lane >> 4) << 3);       // B-frag non-trans (K)
    const int b_kg = (lane >> 3) & 1;
    const int vt_k = (lane & 7) + (((lane >> 3) & 1) << 3); // B-frag trans (V)
    const int vt_n = (lane >> 4);

    const int lrow = tid >> 3, lseg = tid & 7;

    const __half* qb = Q + ((size_t)bh * T_SZ + q0) * HD;
    const __half* kb = K + (size_t)bh * T_SZ * HD;
    const __half* vb = V + (size_t)bh * T_SZ * HD;

    auto LOAD_KV = [&](int k0, int bf){
        const uint32_t Kd = KV0 + (uint32_t)bf * 2*FTILE;
        #pragma unroll
        for (int p = 0; p < 4; p++){
            const int row = lrow + 16*p;
            const uint32_t off = (uint32_t)(row*8 + (lseg ^ (row & 7))) << 4;
            CP16(Kd + off,         kb + (size_t)(k0 + row)*HD + lseg*8);
            CP16(Kd + FTILE + off, vb + (size_t)(k0 + row)*HD + lseg*8);
        }
        CP_COMMIT();
    };

    {   // Q tile: plain swizzled copy (published at first loop barrier)
        uint4* Qs = (uint4*)fsm;
        #pragma unroll
        for (int p = 0; p < 4; p++){
            const int row = lrow + 16*p;
            Qs[row*8 + (lseg ^ (row & 7))] = *(const uint4*)(qb + (size_t)row*HD + lseg*8);
        }
    }

    float m0 = -1e30f, m1 = -1e30f;
    float acc[8][4] = {};
    float accl[4] = {};           // ones-mma row sums: [0]=l(gid), [2]=l(gid+8)
    const uint32_t onesb[2] = { 0x3C003C00u, 0x3C003C00u };   // fp16 1.0 x2

    const int qi0 = q0 + wrow + gid, qi1 = qi0 + 8;

    // per-tile body; diag folds at inlined call sites
    auto BODY = [&](int k0, int bf, bool diag){
        const uint32_t Ku = KV0 + (uint32_t)bf * 2*FTILE;
        const uint32_t Vu = Ku + FTILE;

        // S = Q K^T
        float s[8][4] = {};
        #pragma unroll
        for (int ch = 0; ch < 4; ch++){
            const int cb = ch * 2;
            uint32_t af[4];
            {
                const int row = wrow + a_m;
                ldsm4(af, Qu + row*128 + (((cb + a_kg) ^ (row & 7)) << 4));
            }
            #pragma unroll
            for (int j = 0; j < 4; j++){
                uint32_t bfr[4];
                const int row = j*16 + b_n;
                ldsm4(bfr, Ku + row*128 + (((cb + b_kg) ^ (row & 7)) << 4));
                mma16(s[2*j  ], af, bfr);
                mma16(s[2*j+1], af, bfr + 2);
            }
        }

        // ALiBi (strength-reduced) + optional causal mask + online softmax
        const float bb0 = slope2 * (float)(k0 + 2*tig - qi0);
        const float bb1 = slope2 * (float)(k0 + 2*tig - qi1);
        float mx0 = -1e30f, mx1 = -1e30f;
        #pragma unroll
        for (int nt = 0; nt < 8; nt++){
            #pragma unroll
            for (int e = 0; e < 2; e++){
                const float cf = (float)(nt*8 + e);
                float sv0 = fmaf(s[nt][e],   scale2, fmaf(cf, slope2, bb0));
                float sv1 = fmaf(s[nt][2+e], scale2, fmaf(cf, slope2, bb1));
                if (diag){
                    const int ki = k0 + nt*8 + 2*tig + e;
                    if (ki > qi0) sv0 = -1e30f;
                    if (ki > qi1) sv1 = -1e30f;
                }
                s[nt][e] = sv0; s[nt][2+e] = sv1;
                mx0 = fmaxf(mx0, sv0); mx1 = fmaxf(mx1, sv1);
            }
        }
        mx0 = fmaxf(mx0, __shfl_xor_sync(0xffffffffu, mx0, 1));
        mx0 = fmaxf(mx0, __shfl_xor_sync(0xffffffffu, mx0, 2));
        mx1 = fmaxf(mx1, __shfl_xor_sync(0xffffffffu, mx1, 1));
        mx1 = fmaxf(mx1, __shfl_xor_sync(0xffffffffu, mx1, 2));
        const float mn0 = fmaxf(m0, mx0), mn1 = fmaxf(m1, mx1);

        // warp-vote: skip rescale when max unchanged for ALL lanes (corr==1)
        const bool nochg = (mn0 == m0) && (mn1 == m1);
        if (!__all_sync(0xffffffffu, nochg)){
            const float corr0 = exp2f(m0 - mn0), corr1 = exp2f(m1 - mn1);
            accl[0] *= corr0; accl[2] *= corr1;
            #pragma unroll
            for (int nt = 0; nt < 8; nt++){
                acc[nt][0] *= corr0; acc[nt][1] *= corr0;
                acc[nt][2] *= corr1; acc[nt][3] *= corr1;
            }
        }
        m0 = mn0; m1 = mn1;

        // exp via fp16x2 EX2: subtract m in fp32, pack, one EX2 per pair.
        // P emerges already packed into A-fragments.
        uint32_t pfr[4][4];
        #pragma unroll
        for (int nt = 0; nt < 8; nt++){
            const int ch = nt >> 1, hi = nt & 1;
            pfr[ch][2*hi    ] = ex2h2(pk(s[nt][0] - m0, s[nt][1] - m0));
            pfr[ch][2*hi + 1] = ex2h2(pk(s[nt][2] - m1, s[nt][3] - m1));
        }

        // acc += P @ V  and  accl += P @ 1 (constant ones B-frag -> row sums)
        #pragma unroll
        for (int ch = 0; ch < 4; ch++){
            const int tbase = ch * 16;
            #pragma unroll
            for (int j = 0; j < 4; j++){
                uint32_t bfr[4];
                const int row = tbase + vt_k;
                const int cchunk = (j*2 + vt_n) ^ (row & 7);
                ldsm4t(bfr, Vu + row*128 + (cchunk << 4));
                mma16(acc[2*j  ], pfr[ch], bfr);
                mma16(acc[2*j+1], pfr[ch], bfr + 2);
            }
            mma16(accl, pfr[ch], onesb);
        }
    };

    const int nkt = qt + 1;
    LOAD_KV((nkt-1)*64, (nkt-1)&1);     // diagonal tile first

    {   // peeled diagonal (masked) tile
        CP_WAIT0();
        __syncthreads();
        if (nkt > 1) LOAD_KV((nkt-2)*64, (nkt-2)&1);
        BODY((nkt-1)*64, (nkt-1)&1, true);
    }
    for (int kt = nkt-2; kt >= 0; kt--){   // mask-free tiles, descending
        CP_WAIT0();
        __syncthreads();
        if (kt > 0) LOAD_KV((kt-1)*64, (kt-1)&1);
        BODY(kt*64, kt&1, false);
    }

    const float i0 = 1.f / accl[0], i1 = 1.f / accl[2];
    const size_t mrow = (size_t)(b*T_SZ) + q0 + wrow;
    #pragma unroll
    for (int nt = 0; nt < 8; nt++){
        const int c = nt*8 + 2*tig;
        const int wc = (h*HD + c) >> 1;
        Yw[(mrow + gid    )*(C_SZ/2) + wc] = pk(acc[nt][0]*i0, acc[nt][1]*i0);
        Yw[(mrow + gid + 8)*(C_SZ/2) + wc] = pk(acc[nt][2]*i1, acc[nt][3]*i1);
    }
}

extern "C" void kernel_launch(void* const* d_in, const int* in_sizes, int n_in,
                              void* d_out, int out_size)
{
    const float* x  = (const float*)d_in[0];
    const float* Wq = (const float*)d_in[1];
    const float* bq = (const float*)d_in[2];
    const float* Wk = (const float*)d_in[3];
    const float* bk = (const float*)d_in[4];
    const float* Wv = (const float*)d_in[5];
    const float* bv = (const float*)d_in[6];
    const float* Wo = (const float*)d_in[7];
    const float* bo = (const float*)d_in[8];
    float* out = (float*)d_out;

    __half *xhp, *qp, *kp, *vp, *yhp; uint32_t *wtp;
    cudaGetSymbolAddress((void**)&xhp, g_xh);
    cudaGetSymbolAddress((void**)&wtp, g_wt);
    cudaGetSymbolAddress((void**)&qp,  g_qh);
    cudaGetSymbolAddress((void**)&kp,  g_kh);
    cudaGetSymbolAddress((void**)&vp,  g_vh);
    cudaGetSymbolAddress((void**)&yhp, g_yh);

    cudaFuncSetAttribute(lm_gemm<0>, cudaFuncAttributeMaxDynamicSharedMemorySize, GDYN);
    cudaFuncSetAttribute(lm_gemm<1>, cudaFuncAttributeMaxDynamicSharedMemorySize, GDYN);
    cudaFuncSetAttribute(flash_tc, cudaFuncAttributeMaxDynamicSharedMemorySize, FLASH_SMEM);

    prep_x<<<2048, 256>>>(x, (uint32_t*)xhp);
    prep_w<<<dim3(16, 16, 4), 256>>>(Wq, Wk, Wv, Wo, wtp);

    lm_gemm<0><<<dim3(24, 32), 256, GDYN>>>(xhp, wtp, bq, bk, bv,
                                            (void*)qp, (void*)kp, (void*)vp);

    flash_tc<<<dim3(T_SZ/64, NH, B_SZ), 128, FLASH_SMEM>>>(qp, kp, vp, (uint32_t*)yhp);

    lm_gemm<1><<<dim3(8, 32), 256, GDYN>>>(yhp, wtp, bo, nullptr, nullptr,
                                           (void*)out, nullptr, nullptr);
}

// round 16
// speedup vs baseline: 1.4528x; 1.0329x over previous
#include <cuda_runtime.h>
#include <cuda_fp16.h>
#include <math.h>
#include <stdint.h>

#define B_SZ 2
#define T_SZ 2048
#define C_SZ 1024
#define NH   16
#define HD   64
#define M_SZ (B_SZ*T_SZ)   // 4096
#define LOG2E 1.44269504f

// Scratch (static device globals: allowed; runtime allocation is not)
__device__ __align__(256) __half   g_xh[M_SZ*C_SZ];           // x as fp16 [m][k]
__device__ __align__(256) uint32_t g_wt[4*C_SZ*(C_SZ/2)];     // W^T fp16 [w][n][k2] words
__device__ __align__(256) __half   g_qh[B_SZ*NH*T_SZ*HD];     // [bh][t][d]
__device__ __align__(256) __half   g_kh[B_SZ*NH*T_SZ*HD];     // [bh][t][d]
__device__ __align__(256) __half   g_vh[B_SZ*NH*T_SZ*HD];     // [bh][t][d]
__device__ __align__(256) __half   g_yh[M_SZ*C_SZ];           // attention out fp16 [m][c]

// ---------------------------------------------------------------------------
// helpers
// ---------------------------------------------------------------------------
__device__ __forceinline__ uint32_t pk(float lo, float hi){
    uint32_t r; asm("cvt.rn.f16x2.f32 %0, %1, %2;" : "=r"(r) : "f"(hi), "f"(lo));
    return r;
}
__device__ __forceinline__ uint32_t ex2h2(uint32_t x){
    uint32_t r; asm("ex2.approx.f16x2 %0, %1;" : "=r"(r) : "r"(x));
    return r;
}
__device__ __forceinline__ uint32_t smem_u32(const void* p){
    uint32_t a;
    asm("{ .reg .u64 t; cvta.to.shared.u64 t, %1; cvt.u32.u64 %0, t; }"
        : "=r"(a) : "l"(p));
    return a;
}

#define CP16(dst, src) \
    asm volatile("cp.async.cg.shared.global [%0], [%1], 16;" \
                 :: "r"(dst), "l"(src) : "memory")
#define CP_COMMIT()  asm volatile("cp.async.commit_group;" ::: "memory")
#define CP_WAIT0()   asm volatile("cp.async.wait_group 0;" ::: "memory")
#define CP_WAIT1()   asm volatile("cp.async.wait_group 1;" ::: "memory")

// m16n8k16 fp16 mma, fp32 accumulate, D += A*B (C aliased to D)
__device__ __forceinline__ void mma16(float* d, const uint32_t* a, const uint32_t* b){
    asm volatile("mma.sync.aligned.m16n8k16.row.col.f32.f16.f16.f32 "
        "{%0,%1,%2,%3}, {%4,%5,%6,%7}, {%8,%9}, {%0,%1,%2,%3};"
        : "+f"(d[0]), "+f"(d[1]), "+f"(d[2]), "+f"(d[3])
        : "r"(a[0]), "r"(a[1]), "r"(a[2]), "r"(a[3]), "r"(b[0]), "r"(b[1]));
}

__device__ __forceinline__ void ldsm4(uint32_t* r, uint32_t saddr){
    asm volatile("ldmatrix.sync.aligned.m8n8.x4.shared.b16 {%0,%1,%2,%3}, [%4];"
        : "=r"(r[0]), "=r"(r[1]), "=r"(r[2]), "=r"(r[3]) : "r"(saddr));
}
__device__ __forceinline__ void ldsm4t(uint32_t* r, uint32_t saddr){
    asm volatile("ldmatrix.sync.aligned.m8n8.x4.trans.shared.b16 {%0,%1,%2,%3}, [%4];"
        : "=r"(r[0]), "=r"(r[1]), "=r"(r[2]), "=r"(r[3]) : "r"(saddr));
}

// ---------------------------------------------------------------------------
// fused prep: blocks [0,2048) convert x -> fp16 [m][k];
//             blocks [2048,3072) transpose W[k][n] fp32 -> W^T [n][k] fp16.
// ---------------------------------------------------------------------------
__global__ void prep_all(const float* __restrict__ x, uint32_t* __restrict__ xh,
                         const float* __restrict__ Wq, const float* __restrict__ Wk,
                         const float* __restrict__ Wv, const float* __restrict__ Wo,
                         uint32_t* __restrict__ Wt){
    __shared__ float s[64][65];
    const int tid = threadIdx.x;
    if (blockIdx.x < 2048){
        const int i = blockIdx.x * 256 + tid;
        #pragma unroll
        for (int p = 0; p < 4; p++){
            float2 v = ((const float2*)x)[i + p*524288];
            xh[i + p*524288] = pk(v.x, v.y);
        }
        return;
    }
    const int wb   = blockIdx.x - 2048;
    const int wsel = wb >> 8;
    const int k0   = ((wb >> 4) & 15) * 64, n0 = (wb & 15) * 64;
    const float* W = (wsel==0)?Wq:(wsel==1)?Wk:(wsel==2)?Wv:Wo;
    #pragma unroll
    for (int p = 0; p < 16; p++){
        const int lin = tid + p*256, kk = lin >> 6, nn = lin & 63;
        s[kk][nn] = W[(size_t)(k0+kk)*C_SZ + n0 + nn];
    }
    __syncthreads();
    uint32_t* out = Wt + (size_t)wsel * C_SZ * (C_SZ/2);
    #pragma unroll
    for (int p = 0; p < 8; p++){
        const int lin = tid + p*256, nn = lin >> 5, k2 = lin & 31;
        out[(size_t)(n0+nn)*(C_SZ/2) + (k0 >> 1) + k2] = pk(s[2*k2][nn], s[2*k2+1][nn]);
    }
}

// ---------------------------------------------------------------------------
// fp16 ldmatrix GEMM: 128x128 tile, KC=64, 8 warps (4m x 2n), warp 32x64.
// 3-stage cp.async smem ring, ONE barrier per K-step.
// Swizzle<3,3,3>: 16B chunk c -> c ^ (row&7). MODE 0 = QKV, MODE 1 = O-proj.
// ---------------------------------------------------------------------------
#define MODE_PLAIN   0
#define MODE_HEADS   1
#define KC 64
#define GTILE 16384                 // 128 rows x 128 B
#define GDYN  (6*GTILE)             // A0 A1 A2 B0 B1 B2 = 96 KB

template<int MODE>
__global__ __launch_bounds__(256, 2)
void lm_gemm(const __half* __restrict__ Aall, const uint32_t* __restrict__ Wt,
             const float* __restrict__ b0, const float* __restrict__ b1,
             const float* __restrict__ b2,
             void* __restrict__ o0, void* __restrict__ o1, void* __restrict__ o2)
{
    extern __shared__ char dsm[];
    const uint32_t sm0 = smem_u32(dsm);

    const int tid  = threadIdx.x;
    const int warp = tid >> 5, lane = tid & 31;
    const int gid  = lane >> 2, tig = lane & 3;
    const int warpM = (warp & 3) * 32, warpN = (warp >> 2) * 64;

    int which, bn, bm; const float* bias; void* outv;
    if (MODE == 0){
        which = blockIdx.x >> 3;
        bn = (blockIdx.x & 7) * 128;
        bm = blockIdx.y * 128;
        bias = (which==0)?b0:(which==1)?b1:b2;
        outv = (which==0)?o0:(which==1)?o1:o2;
    } else {
        which = 3; bn = blockIdx.x * 128; bm = blockIdx.y * 128;
        bias = b0; outv = o0;
    }

    const int a_m  = lane & 15, a_kg = lane >> 4;
    const int b_n  = (lane & 7) + ((lane >> 4) << 3);
    const int b_kg = (lane >> 3) & 1;
    const int lrow = tid >> 3, lseg = tid & 7;

    const __half*   Ah = Aall + (size_t)bm * C_SZ;
    const uint32_t* Bw = Wt + ((size_t)which * C_SZ + bn) * (C_SZ/2);

    auto LOAD = [&](int k0, int s){
        const uint32_t Au = sm0 + s*GTILE;
        const uint32_t Bu = sm0 + 3*GTILE + s*GTILE;
        #pragma unroll
        for (int p = 0; p < 4; p++){
            const int row = lrow + 32*p;
            const uint32_t off = (uint32_t)(row*8 + (lseg ^ (row & 7))) << 4;
            CP16(Au + off, Ah + (size_t)row*C_SZ + k0 + lseg*8);
            CP16(Bu + off, Bw + (size_t)row*(C_SZ/2) + (k0>>1) + lseg*4);
        }
        CP_COMMIT();
    };

    float acc[2][8][4];
    #pragma unroll
    for (int mt = 0; mt < 2; mt++)
        #pragma unroll
        for (int nt = 0; nt < 8; nt++)
            #pragma unroll
            for (int e = 0; e < 4; e++) acc[mt][nt][e] = 0.f;

    auto COMPUTE = [&](int s){
        const uint32_t Au = sm0 + s*GTILE;
        const uint32_t Bu = sm0 + 3*GTILE + s*GTILE;
        #pragma unroll
        for (int kw = 0; kw < KC; kw += 16){
            const int cb = kw >> 3;
            uint32_t a[2][4];
            #pragma unroll
            for (int mt = 0; mt < 2; mt++){
                const int row = warpM + mt*16 + a_m;
                ldsm4(a[mt], Au + row*128 + (((cb + a_kg) ^ (row & 7)) << 4));
            }
            #pragma unroll
            for (int j = 0; j < 4; j++){
                uint32_t bf[4];
                const int row = warpN + j*16 + b_n;
                ldsm4(bf, Bu + row*128 + (((cb + b_kg) ^ (row & 7)) << 4));
                mma16(acc[0][2*j  ], a[0], bf);
                mma16(acc[0][2*j+1], a[0], bf + 2);
                mma16(acc[1][2*j  ], a[1], bf);
                mma16(acc[1][2*j+1], a[1], bf + 2);
            }
        }
    };

    LOAD(0, 0);
    LOAD(KC, 1);
    for (int i = 0; i < 16; i++){
        CP_WAIT1();          // tile i complete (tile i+1 may remain in flight)
        __syncthreads();     // all warps finished compute i-1 (buffer reuse safe)
        if (i + 2 < 16) LOAD((i+2)*KC, (i+2)%3);
        COMPUTE(i%3);
    }

    #pragma unroll
    for (int mt = 0; mt < 2; mt++){
        #pragma unroll
        for (int nt = 0; nt < 8; nt++){
            const int r = bm + warpM + mt*16 + gid;
            const int c = bn + warpN + nt*8 + 2*tig;
            const float b0v = bias[c], b1v = bias[c+1];
            float2 v0 = make_float2(acc[mt][nt][0] + b0v, acc[mt][nt][1] + b1v);
            float2 v1 = make_float2(acc[mt][nt][2] + b0v, acc[mt][nt][3] + b1v);
            if (MODE == 1){
                float* out = (float*)outv;
                *(float2*)&out[(size_t)r * C_SZ + c]     = v0;
                *(float2*)&out[(size_t)(r+8) * C_SZ + c] = v1;
            } else {
                const int b = r >> 11, t = r & 2047;
                const int h = c >> 6,  d = c & 63;
                const int bh = b*NH + h;
                __half* out = (__half*)outv;
                *(uint32_t*)&out[((size_t)bh * T_SZ + t    ) * HD + d] = pk(v0.x, v0.y);
                *(uint32_t*)&out[((size_t)bh * T_SZ + t + 8) * HD + d] = pk(v1.x, v1.y);
            }
        }
    }
}

// ---------------------------------------------------------------------------
// Flash attention, fp16 mma, BQ=64, BK=64, P in registers, ldmatrix frags,
// cp.async double-buffered K/V, diagonal-first K order, ones-mma row sums.
// R15: -m folded into the ALiBi bias constant (scores emerge pre-subtracted,
//      new-max test is mx>0); vote-then-reduce replaces the per-tile 4-SHFL
//      max reduction on the common path (rare path does exact rescale).
// ---------------------------------------------------------------------------
#define FTILE 8192   // 64 rows x 128 B
#define FLASH_SMEM (5*FTILE)

__global__ __launch_bounds__(128, 4)
void flash_tc(const __half* __restrict__ Q, const __half* __restrict__ K,
              const __half* __restrict__ V, uint32_t* __restrict__ Yw)
{
    extern __shared__ char fsm[];
    const uint32_t Qu  = smem_u32(fsm);
    const uint32_t KV0 = Qu + FTILE;           // [K0][V0][K1][V1]

    const int tid  = threadIdx.x;
    const int warp = tid >> 5, lane = tid & 31;
    const int gid  = lane >> 2, tig = lane & 3;
    const int qt   = (int)gridDim.x - 1 - (int)blockIdx.x;   // heavy first
    const int h    = blockIdx.y, b = blockIdx.z;
    const int bh   = b * NH + h;
    const int q0   = qt * 64;
    const int wrow = warp * 16;
    const float slope2 = exp2f(-0.5f * (float)(h + 1)) * LOG2E;
    const float scale2 = 0.125f * LOG2E;

    const int a_m  = lane & 15, a_kg = lane >> 4;           // A-frag (Q)
    const int b_n  = (lane & 7) + ((lane >> 4) << 3);       // B-frag non-trans (K)
    const int b_kg = (lane >> 3) & 1;
    const int vt_k = (lane & 7) + (((lane >> 3) & 1) << 3); // B-frag trans (V)
    const int vt_n = (lane >> 4);

    const int lrow = tid >> 3, lseg = tid & 7;

    const __half* qb = Q + ((size_t)bh * T_SZ + q0) * HD;
    const __half* kb = K + (size_t)bh * T_SZ * HD;
    const __half* vb = V + (size_t)bh * T_SZ * HD;

    auto LOAD_KV = [&](int k0, int bf){
        const uint32_t Kd = KV0 + (uint32_t)bf * 2*FTILE;
        #pragma unroll
        for (int p = 0; p < 4; p++){
            const int row = lrow + 16*p;
            const uint32_t off = (uint32_t)(row*8 + (lseg ^ (row & 7))) << 4;
            CP16(Kd + off,         kb + (size_t)(k0 + row)*HD + lseg*8);
            CP16(Kd + FTILE + off, vb + (size_t)(k0 + row)*HD + lseg*8);
        }
        CP_COMMIT();
    };

    {   // Q tile: plain swizzled copy (published at first loop barrier)
        uint4* Qs = (uint4*)fsm;
        #pragma unroll
        for (int p = 0; p < 4; p++){
            const int row = lrow + 16*p;
            Qs[row*8 + (lseg ^ (row & 7))] = *(const uint4*)(qb + (size_t)row*HD + lseg*8);
        }
    }

    float m0 = 0.f, m1 = 0.f;    // set by the (always-first) diagonal tile
    float acc[8][4] = {};
    float accl[4] = {};          // ones-mma row sums: [0]=l(gid), [2]=l(gid+8)
    const uint32_t onesb[2] = { 0x3C003C00u, 0x3C003C00u };   // fp16 1.0 x2

    const int qi0 = q0 + wrow + gid, qi1 = qi0 + 8;

    // per-tile body; diag folds at inlined call sites (diag == first tile)
    auto BODY = [&](int k0, int bf, bool diag){
        const uint32_t Ku = KV0 + (uint32_t)bf * 2*FTILE;
        const uint32_t Vu = Ku + FTILE;

        // S = Q K^T
        float s[8][4] = {};
        #pragma unroll
        for (int ch = 0; ch < 4; ch++){
            const int cb = ch * 2;
            uint32_t af[4];
            {
                const int row = wrow + a_m;
                ldsm4(af, Qu + row*128 + (((cb + a_kg) ^ (row & 7)) << 4));
            }
            #pragma unroll
            for (int j = 0; j < 4; j++){
                uint32_t bfr[4];
                const int row = j*16 + b_n;
                ldsm4(bfr, Ku + row*128 + (((cb + b_kg) ^ (row & 7)) << 4));
                mma16(s[2*j  ], af, bfr);
                mma16(s[2*j+1], af, bfr + 2);
            }
        }

        uint32_t pfr[4][4];
        if (diag){
            // first tile: causal mask + full max reduce, sets m (acc == 0)
            const float bb0 = slope2 * (float)(k0 + 2*tig - qi0);
            const float bb1 = slope2 * (float)(k0 + 2*tig - qi1);
            float mx0 = -1e30f, mx1 = -1e30f;
            #pragma unroll
            for (int nt = 0; nt < 8; nt++){
                #pragma unroll
                for (int e = 0; e < 2; e++){
                    const float cf = (float)(nt*8 + e);
                    float sv0 = fmaf(s[nt][e],   scale2, fmaf(cf, slope2, bb0));
                    float sv1 = fmaf(s[nt][2+e], scale2, fmaf(cf, slope2, bb1));
                    const int ki = k0 + nt*8 + 2*tig + e;
                    if (ki > qi0) sv0 = -1e30f;
                    if (ki > qi1) sv1 = -1e30f;
                    s[nt][e] = sv0; s[nt][2+e] = sv1;
                    mx0 = fmaxf(mx0, sv0); mx1 = fmaxf(mx1, sv1);
                }
            }
            mx0 = fmaxf(mx0, __shfl_xor_sync(0xffffffffu, mx0, 1));
            mx0 = fmaxf(mx0, __shfl_xor_sync(0xffffffffu, mx0, 2));
            mx1 = fmaxf(mx1, __shfl_xor_sync(0xffffffffu, mx1, 1));
            mx1 = fmaxf(mx1, __shfl_xor_sync(0xffffffffu, mx1, 2));
            m0 = mx0; m1 = mx1;
            #pragma unroll
            for (int nt = 0; nt < 8; nt++){
                const int ch = nt >> 1, hi = nt & 1;
                pfr[ch][2*hi    ] = ex2h2(pk(s[nt][0] - m0, s[nt][1] - m0));
                pfr[ch][2*hi + 1] = ex2h2(pk(s[nt][2] - m1, s[nt][3] - m1));
            }
        } else {
            // -m folded into bias: scores emerge pre-subtracted; new max <=> >0
            const float bb0 = slope2 * (float)(k0 + 2*tig - qi0) - m0;
            const float bb1 = slope2 * (float)(k0 + 2*tig - qi1) - m1;
            float mx0 = -1e30f, mx1 = -1e30f;
            #pragma unroll
            for (int nt = 0; nt < 8; nt++){
                #pragma unroll
                for (int e = 0; e < 2; e++){
                    const float cf = (float)(nt*8 + e);
                    const float sv0 = fmaf(s[nt][e],   scale2, fmaf(cf, slope2, bb0));
                    const float sv1 = fmaf(s[nt][2+e], scale2, fmaf(cf, slope2, bb1));
                    s[nt][e] = sv0; s[nt][2+e] = sv1;
                    mx0 = fmaxf(mx0, sv0); mx1 = fmaxf(mx1, sv1);
                }
            }
            const bool over = (mx0 > 0.f) || (mx1 > 0.f);
            if (__any_sync(0xffffffffu, over)){   // rare: max grew
                mx0 = fmaxf(mx0, __shfl_xor_sync(0xffffffffu, mx0, 1));
                mx0 = fmaxf(mx0, __shfl_xor_sync(0xffffffffu, mx0, 2));
                mx1 = fmaxf(mx1, __shfl_xor_sync(0xffffffffu, mx1, 1));
                mx1 = fmaxf(mx1, __shfl_xor_sync(0xffffffffu, mx1, 2));
                const float d0 = fmaxf(mx0, 0.f), d1 = fmaxf(mx1, 0.f);
                m0 += d0; m1 += d1;
                const float c0 = exp2f(-d0), c1 = exp2f(-d1);
                accl[0] *= c0; accl[2] *= c1;
                #pragma unroll
                for (int nt = 0; nt < 8; nt++){
                    acc[nt][0] *= c0; acc[nt][1] *= c0;
                    acc[nt][2] *= c1; acc[nt][3] *= c1;
                    s[nt][0] -= d0; s[nt][1] -= d0;
                    s[nt][2] -= d1; s[nt][3] -= d1;
                }
            }
            #pragma unroll
            for (int nt = 0; nt < 8; nt++){
                const int ch = nt >> 1, hi = nt & 1;
                pfr[ch][2*hi    ] = ex2h2(pk(s[nt][0], s[nt][1]));
                pfr[ch][2*hi + 1] = ex2h2(pk(s[nt][2], s[nt][3]));
            }
        }

        // acc += P @ V  and  accl += P @ 1 (constant ones B-frag -> row sums)
        #pragma unroll
        for (int ch = 0; ch < 4; ch++){
            const int tbase = ch * 16;
            #pragma unroll
            for (int j = 0; j < 4; j++){
                uint32_t bfr[4];
                const int row = tbase + vt_k;
                const int cchunk = (j*2 + vt_n) ^ (row & 7);
                ldsm4t(bfr, Vu + row*128 + (cchunk << 4));
                mma16(acc[2*j  ], pfr[ch], bfr);
                mma16(acc[2*j+1], pfr[ch], bfr + 2);
            }
            mma16(accl, pfr[ch], onesb);
        }
    };

    const int nkt = qt + 1;
    LOAD_KV((nkt-1)*64, (nkt-1)&1);     // diagonal tile first

    {   // peeled diagonal (masked) tile
        CP_WAIT0();
        __syncthreads();
        if (nkt > 1) LOAD_KV((nkt-2)*64, (nkt-2)&1);
        BODY((nkt-1)*64, (nkt-1)&1, true);
    }
    for (int kt = nkt-2; kt >= 0; kt--){   // mask-free tiles, descending
        CP_WAIT0();
        __syncthreads();
        if (kt > 0) LOAD_KV((kt-1)*64, (kt-1)&1);
        BODY(kt*64, kt&1, false);
    }

    const float i0 = 1.f / accl[0], i1 = 1.f / accl[2];
    const size_t mrow = (size_t)(b*T_SZ) + q0 + wrow;
    #pragma unroll
    for (int nt = 0; nt < 8; nt++){
        const int c = nt*8 + 2*tig;
        const int wc = (h*HD + c) >> 1;
        Yw[(mrow + gid    )*(C_SZ/2) + wc] = pk(acc[nt][0]*i0, acc[nt][1]*i0);
        Yw[(mrow + gid + 8)*(C_SZ/2) + wc] = pk(acc[nt][2]*i1, acc[nt][3]*i1);
    }
}

extern "C" void kernel_launch(void* const* d_in, const int* in_sizes, int n_in,
                              void* d_out, int out_size)
{
    const float* x  = (const float*)d_in[0];
    const float* Wq = (const float*)d_in[1];
    const float* bq = (const float*)d_in[2];
    const float* Wk = (const float*)d_in[3];
    const float* bk = (const float*)d_in[4];
    const float* Wv = (const float*)d_in[5];
    const float* bv = (const float*)d_in[6];
    const float* Wo = (const float*)d_in[7];
    const float* bo = (const float*)d_in[8];
    float* out = (float*)d_out;

    __half *xhp, *qp, *kp, *vp, *yhp; uint32_t *wtp;
    cudaGetSymbolAddress((void**)&xhp, g_xh);
    cudaGetSymbolAddress((void**)&wtp, g_wt);
    cudaGetSymbolAddress((void**)&qp,  g_qh);
    cudaGetSymbolAddress((void**)&kp,  g_kh);
    cudaGetSymbolAddress((void**)&vp,  g_vh);
    cudaGetSymbolAddress((void**)&yhp, g_yh);

    cudaFuncSetAttribute(lm_gemm<0>, cudaFuncAttributeMaxDynamicSharedMemorySize, GDYN);
    cudaFuncSetAttribute(lm_gemm<1>, cudaFuncAttributeMaxDynamicSharedMemorySize, GDYN);
    cudaFuncSetAttribute(flash_tc, cudaFuncAttributeMaxDynamicSharedMemorySize, FLASH_SMEM);

    prep_all<<<3072, 256>>>(x, (uint32_t*)xhp, Wq, Wk, Wv, Wo, wtp);

    lm_gemm<0><<<dim3(24, 32), 256, GDYN>>>(xhp, wtp, bq, bk, bv,
                                            (void*)qp, (void*)kp, (void*)vp);

    flash_tc<<<dim3(T_SZ/64, NH, B_SZ), 128, FLASH_SMEM>>>(qp, kp, vp, (uint32_t*)yhp);

    lm_gemm<1><<<dim3(8, 32), 256, GDYN>>>(yhp, wtp, bo, nullptr, nullptr,
                                           (void*)out, nullptr, nullptr);
}